// round 6
// baseline (speedup 1.0000x reference)
#include <cuda_runtime.h>
#include <cuda_bf16.h>
#include <math.h>

// ---------------------------------------------------------------------------
// MambaLayer: B=2, L=2048, D_MODEL=1024, D_INNER=2048, D_STATE=8, D_CONV=4,
// DT_RANK=64.  NTOK = B*L = 4096.
//
//  1) xz    = x @ W_in                         GEMM [4096,1024]x[1024,4096]
//  2) xcpre = causal depthwise conv(x_in)      elementwise
//  3) xc    = silu(xcpre @ pw + conv_bias)     GEMM [4096,2048]x[2048,2048]
//  4) xdbl  = xc @ W_x                         GEMM [4096,2048]x[2048,80] splitK
//  5) delta = softplus(xdbl[:,:64]@W_dt+b_dt)  GEMM [4096,64]x[64,2048]
//  6) selective scan over L (chunked, cp.async double buffered), fused with
//     y = (scan_y + xc*D) * silu(z)
//  7) out   = y @ W_out                        GEMM [4096,2048]x[2048,1024]
// ---------------------------------------------------------------------------

#define NTOK   4096
#define DI     2048
#define DM     1024
#define NDBL   80       // DT_RANK + 2*D_STATE
#define DTR    64
#define DST    8
#define NSPLIT 8
#define LSEQ   2048

// ---------------- scratch (device globals: no runtime allocs) --------------
__device__ float g_xz   [(size_t)NTOK * 2 * DI];
__device__ float g_xcpre[(size_t)NTOK * DI];
__device__ float g_xc   [(size_t)NTOK * DI];
__device__ float g_xdbl [(size_t)NTOK * NDBL];
__device__ float g_part [(size_t)NSPLIT * NTOK * NDBL];
__device__ float g_delta[(size_t)NTOK * DI];
__device__ float g_y    [(size_t)NTOK * DI];

// ---------------- packed f32x2 helpers -------------------------------------
__device__ __forceinline__ unsigned long long pack2(float lo, float hi) {
    unsigned long long r;
    asm("mov.b64 %0, {%1, %2};" : "=l"(r) : "f"(lo), "f"(hi));
    return r;
}
__device__ __forceinline__ void unpack2(unsigned long long v, float &lo, float &hi) {
    asm("mov.b64 {%0, %1}, %2;" : "=f"(lo), "=f"(hi) : "l"(v));
}
__device__ __forceinline__ void ffma2(unsigned long long &d,
                                      unsigned long long a,
                                      unsigned long long b) {
    // d = a*b + d on two packed fp32 lanes (FFMA2: full-rate fp32 on sm_103a)
    asm("fma.rn.f32x2 %0, %1, %2, %0;" : "+l"(d) : "l"(a), "l"(b));
}

__device__ __forceinline__ void cp16(void* s, const void* g) {
    unsigned saddr = (unsigned)__cvta_generic_to_shared(s);
    asm volatile("cp.async.ca.shared.global [%0], [%1], 16;" :: "r"(saddr), "l"(g));
}

__device__ __forceinline__ float apply_epi(float x, int epi) {
    if (epi == 1) return x / (1.f + expf(-x));                  // silu
    if (epi == 2) return (x > 20.f) ? x : log1pf(expf(x));      // softplus
    return x;
}

// ---------------- generic tiled SGEMM (row-major) --------------------------
// C[M,N] = A[M,K] * B[K,N].  Optional bias+activation epilogue.
// Optional split-K via grid.z: each z computes K-range [z*kChunk, ...) and
// writes to C + z*zstride (partials reduced later, deterministic).
#define BM 128
#define BN 128
#define BK 16

__global__ __launch_bounds__(256)
void sgemm_kernel(const float* __restrict__ A, int lda,
                  const float* __restrict__ B, int ldb,
                  float* __restrict__ C, int ldc, long long zstride,
                  int M, int N, int K, int kChunk,
                  const float* __restrict__ bias, int epi)
{
    __shared__ float As[BK][BM + 4];
    __shared__ float Bs[BK][BN];

    const int tid = threadIdx.x;
    const int ty = tid >> 4;          // 0..15
    const int tx = tid & 15;          // 0..15
    const int m0 = blockIdx.y * BM;
    const int n0 = blockIdx.x * BN;
    const int k0 = blockIdx.z * kChunk;
    const int k1 = (k0 + kChunk < K) ? (k0 + kChunk) : K;
    C += (long long)blockIdx.z * zstride;

    const bool guardN = (n0 + BN > N);

    // A tile: 128 rows x 16 cols = 512 float4; this thread handles q=tid, tid+256
    const int a_r0 = tid >> 2,          a_c0 = (tid & 3) << 2;
    const int a_r1 = (tid + 256) >> 2,  a_c1 = ((tid + 256) & 3) << 2;
    // B tile: 16 rows x 128 cols = 512 float4
    const int b_r0 = tid >> 5,          b_c0 = (tid & 31) << 2;
    const int b_r1 = (tid + 256) >> 5,  b_c1 = ((tid + 256) & 31) << 2;

    float4 avA, avB, bvA, bvB;
    float bsc[8];

    unsigned long long acc[8][4];
#pragma unroll
    for (int i = 0; i < 8; ++i)
#pragma unroll
        for (int j = 0; j < 4; ++j) acc[i][j] = 0ull;

#define LOAD_TILE(kb) do {                                                       \
    avA = *(const float4*)&A[(size_t)(m0 + a_r0) * lda + (kb) + a_c0];           \
    avB = *(const float4*)&A[(size_t)(m0 + a_r1) * lda + (kb) + a_c1];           \
    if (!guardN) {                                                               \
        bvA = *(const float4*)&B[(size_t)((kb) + b_r0) * ldb + n0 + b_c0];       \
        bvB = *(const float4*)&B[(size_t)((kb) + b_r1) * ldb + n0 + b_c1];       \
    } else {                                                                     \
        _Pragma("unroll")                                                        \
        for (int i_ = 0; i_ < 8; ++i_) {                                         \
            int e_ = i_ * 256 + tid; int r_ = e_ >> 7, c_ = e_ & 127;            \
            bsc[i_] = (n0 + c_ < N) ? B[(size_t)((kb) + r_) * ldb + n0 + c_]     \
                                    : 0.f;                                       \
        }                                                                        \
    } } while (0)

#define STORE_TILE() do {                                                        \
    As[a_c0 + 0][a_r0] = avA.x; As[a_c0 + 1][a_r0] = avA.y;                      \
    As[a_c0 + 2][a_r0] = avA.z; As[a_c0 + 3][a_r0] = avA.w;                      \
    As[a_c1 + 0][a_r1] = avB.x; As[a_c1 + 1][a_r1] = avB.y;                      \
    As[a_c1 + 2][a_r1] = avB.z; As[a_c1 + 3][a_r1] = avB.w;                      \
    if (!guardN) {                                                               \
        *(float4*)&Bs[b_r0][b_c0] = bvA;                                         \
        *(float4*)&Bs[b_r1][b_c1] = bvB;                                         \
    } else {                                                                     \
        _Pragma("unroll")                                                        \
        for (int i_ = 0; i_ < 8; ++i_) {                                         \
            int e_ = i_ * 256 + tid;                                             \
            Bs[e_ >> 7][e_ & 127] = bsc[i_];                                     \
        }                                                                        \
    } } while (0)

    LOAD_TILE(k0);
    STORE_TILE();
    __syncthreads();

    for (int kb = k0; kb < k1; kb += BK) {
        const bool more = (kb + BK < k1);
        if (more) LOAD_TILE(kb + BK);

#pragma unroll
        for (int kk = 0; kk < BK; ++kk) {
            float4 a0 = *(const float4*)&As[kk][ty * 8];
            float4 a1 = *(const float4*)&As[kk][ty * 8 + 4];
            const unsigned long long* bp =
                (const unsigned long long*)&Bs[kk][tx * 8];
            unsigned long long b0 = bp[0], b1 = bp[1], b2 = bp[2], b3 = bp[3];
            float ar[8] = {a0.x, a0.y, a0.z, a0.w, a1.x, a1.y, a1.z, a1.w};
#pragma unroll
            for (int i = 0; i < 8; ++i) {
                unsigned long long aa = pack2(ar[i], ar[i]);
                ffma2(acc[i][0], aa, b0);
                ffma2(acc[i][1], aa, b1);
                ffma2(acc[i][2], aa, b2);
                ffma2(acc[i][3], aa, b3);
            }
        }
        __syncthreads();
        if (more) { STORE_TILE(); __syncthreads(); }
    }

    // epilogue
    const int cbase = n0 + tx * 8;
#pragma unroll
    for (int i = 0; i < 8; ++i) {
        const int row = m0 + ty * 8 + i;
        float v[8];
#pragma unroll
        for (int j = 0; j < 4; ++j) unpack2(acc[i][j], v[2 * j], v[2 * j + 1]);
        if (!guardN) {
#pragma unroll
            for (int t = 0; t < 8; ++t) {
                float xv = v[t];
                if (bias) xv += bias[cbase + t];
                v[t] = apply_epi(xv, epi);
            }
            *(float4*)&C[(size_t)row * ldc + cbase]     = make_float4(v[0], v[1], v[2], v[3]);
            *(float4*)&C[(size_t)row * ldc + cbase + 4] = make_float4(v[4], v[5], v[6], v[7]);
        } else {
#pragma unroll
            for (int t = 0; t < 8; ++t) {
                int col = cbase + t;
                if (col < N) {
                    float xv = v[t];
                    if (bias) xv += bias[col];
                    C[(size_t)row * ldc + col] = apply_epi(xv, epi);
                }
            }
        }
    }
#undef LOAD_TILE
#undef STORE_TILE
}

// ---------------- split-K partial reduce ------------------------------------
__global__ void reduce_kernel(const float* __restrict__ part,
                              float* __restrict__ out)
{
    int i = blockIdx.x * blockDim.x + threadIdx.x;
    if (i < NTOK * NDBL) {
        float s = 0.f;
#pragma unroll
        for (int z = 0; z < NSPLIT; ++z)
            s += part[(size_t)z * NTOK * NDBL + i];
        out[i] = s;
    }
}

// ---------------- causal depthwise conv (D_CONV=4) ---------------------------
// xz layout [t, 4096]: cols 0..2047 = x_in.  out[t,c] = sum_j x_in[t-3+j,c]*dw[j,c]
__global__ __launch_bounds__(256)
void dwconv_kernel(const float* __restrict__ xz,
                   const float* __restrict__ dw,
                   float* __restrict__ out)
{
    int i = blockIdx.x * blockDim.x + threadIdx.x;   // float4 index
    int c = (i & (DI / 4 - 1)) << 2;
    int t = i >> 9;                                   // DI/4 = 512
    int l = t & (LSEQ - 1);
    float4 acc = make_float4(0.f, 0.f, 0.f, 0.f);
#pragma unroll
    for (int j = 0; j < 4; ++j) {
        int lj = l - 3 + j;
        if (lj >= 0) {
            float4 xv = *(const float4*)&xz[(size_t)(t - 3 + j) * 2 * DI + c];
            float4 wv = *(const float4*)&dw[(size_t)j * DI + c];
            acc.x += xv.x * wv.x; acc.y += xv.y * wv.y;
            acc.z += xv.z * wv.z; acc.w += xv.w * wv.w;
        }
    }
    *(float4*)&out[(size_t)t * DI + c] = acc;
}

// ---------------- selective scan (fused epilogue) ---------------------------
// Thread = (channel cl 0..31, state n 0..7).  Block = 32 channels of one batch.
// Chunked over L in 32-step tiles, cp.async double buffered.
__global__ __launch_bounds__(256)
void scan_kernel(const float* __restrict__ delta,
                 const float* __restrict__ xc,
                 const float* __restrict__ xz,
                 const float* __restrict__ xdbl,
                 const float* __restrict__ A_log,
                 const float* __restrict__ Dv,
                 float* __restrict__ y)
{
    __shared__ float sd[2][32][32];
    __shared__ float sx[2][32][32];
    __shared__ float sz[2][32][32];
    __shared__ float sbc[2][32][16];   // [t][0..7]=B, [t][8..15]=C
    __shared__ float sy[32][32];

    const int tid = threadIdx.x;
    const int n   = tid & 7;
    const int cl  = tid >> 3;
    const int c0  = blockIdx.x * 32;
    const int tb  = blockIdx.y * LSEQ;
    const int c   = c0 + cl;

    const float a2 = -expf(A_log[c * DST + n]) * 1.44269504f;   // A * log2(e)
    const float Dc = Dv[c];
    float h = 0.f;

    const int row = tid >> 3;   // 0..31 (t within chunk)
    const int seg = tid & 7;    // 0..7  (16B segment)

    // prefetch chunk 0
    {
        int t = tb + row;
        cp16(&sd[0][row][seg * 4], delta + (size_t)t * DI + c0 + seg * 4);
        cp16(&sx[0][row][seg * 4], xc    + (size_t)t * DI + c0 + seg * 4);
        cp16(&sz[0][row][seg * 4], xz    + (size_t)t * 2 * DI + DI + c0 + seg * 4);
        if (seg < 4)
            cp16(&sbc[0][row][seg * 4], xdbl + (size_t)t * NDBL + DTR + seg * 4);
        asm volatile("cp.async.commit_group;");
    }

    int buf = 0;
    for (int ch = 0; ch < LSEQ / 32; ++ch) {
        if (ch < LSEQ / 32 - 1) {
            int t = tb + (ch + 1) * 32 + row;
            int nb = buf ^ 1;
            cp16(&sd[nb][row][seg * 4], delta + (size_t)t * DI + c0 + seg * 4);
            cp16(&sx[nb][row][seg * 4], xc    + (size_t)t * DI + c0 + seg * 4);
            cp16(&sz[nb][row][seg * 4], xz    + (size_t)t * 2 * DI + DI + c0 + seg * 4);
            if (seg < 4)
                cp16(&sbc[nb][row][seg * 4], xdbl + (size_t)t * NDBL + DTR + seg * 4);
            asm volatile("cp.async.commit_group;");
            asm volatile("cp.async.wait_group 1;");
        } else {
            asm volatile("cp.async.wait_group 0;");
        }
        __syncthreads();

#pragma unroll
        for (int tt = 0; tt < 32; ++tt) {
            float dlt = sd[buf][tt][cl];
            float xcv = sx[buf][tt][cl];
            float dA  = exp2f(dlt * a2);
            float dBu = dlt * sbc[buf][tt][n] * xcv;
            h = fmaf(dA, h, dBu);
            float p = sbc[buf][tt][8 + n] * h;
            p += __shfl_xor_sync(0xffffffffu, p, 1);
            p += __shfl_xor_sync(0xffffffffu, p, 2);
            p += __shfl_xor_sync(0xffffffffu, p, 4);
            if (n == 0) {
                float yv = p + xcv * Dc;
                float zv = sz[buf][tt][cl];
                sy[tt][cl] = yv * (zv / (1.f + expf(-zv)));
            }
        }
        __syncthreads();

        // coalesced flush of the 32x32 y tile
#pragma unroll
        for (int r = 0; r < 4; ++r) {
            int e  = r * 256 + tid;
            int tt = e >> 5, col = e & 31;
            y[(size_t)(tb + ch * 32 + tt) * DI + c0 + col] = sy[tt][col];
        }
        buf ^= 1;
        // sy reuse is protected by next iteration's __syncthreads()
    }
}

// ---------------------------------------------------------------------------
extern "C" void kernel_launch(void* const* d_in, const int* in_sizes, int n_in,
                              void* d_out, int out_size)
{
    const float* x     = (const float*)d_in[0];
    const float* W_in  = (const float*)d_in[1];
    const float* dw    = (const float*)d_in[2];
    const float* pw    = (const float*)d_in[3];
    const float* cb    = (const float*)d_in[4];
    const float* W_x   = (const float*)d_in[5];
    const float* W_dt  = (const float*)d_in[6];
    const float* b_dt  = (const float*)d_in[7];
    const float* A_log = (const float*)d_in[8];
    const float* Dv    = (const float*)d_in[9];
    const float* W_out = (const float*)d_in[10];
    float* out = (float*)d_out;

    // Resolve scratch addresses on EVERY call (no static caching: kernel_launch
    // must behave identically on the correctness call and the capture call).
    float *p_xz, *p_xcpre, *p_xc, *p_xdbl, *p_part, *p_delta, *p_y;
    cudaGetSymbolAddress((void**)&p_xz,    g_xz);
    cudaGetSymbolAddress((void**)&p_xcpre, g_xcpre);
    cudaGetSymbolAddress((void**)&p_xc,    g_xc);
    cudaGetSymbolAddress((void**)&p_xdbl,  g_xdbl);
    cudaGetSymbolAddress((void**)&p_part,  g_part);
    cudaGetSymbolAddress((void**)&p_delta, g_delta);
    cudaGetSymbolAddress((void**)&p_y,     g_y);

    dim3 blk(256);

    // 1) xz = x @ W_in                      [4096,1024] x [1024,4096]
    sgemm_kernel<<<dim3(2 * DI / BN, NTOK / BM), blk>>>(
        x, DM, W_in, 2 * DI, p_xz, 2 * DI, 0, NTOK, 2 * DI, DM, DM, nullptr, 0);

    // 2) depthwise causal conv
    dwconv_kernel<<<(NTOK * DI / 4) / 256, 256>>>(p_xz, dw, p_xcpre);

    // 3) xc = silu(xcpre @ pw + conv_bias)  [4096,2048] x [2048,2048]
    sgemm_kernel<<<dim3(DI / BN, NTOK / BM), blk>>>(
        p_xcpre, DI, pw, DI, p_xc, DI, 0, NTOK, DI, DI, DI, cb, 1);

    // 4) xdbl = xc @ W_x (split-K=8, deterministic partials)
    sgemm_kernel<<<dim3(1, NTOK / BM, NSPLIT), blk>>>(
        p_xc, DI, W_x, NDBL, p_part, NDBL, (long long)NTOK * NDBL,
        NTOK, NDBL, DI, DI / NSPLIT, nullptr, 0);
    reduce_kernel<<<(NTOK * NDBL + 255) / 256, 256>>>(p_part, p_xdbl);

    // 5) delta = softplus(xdbl[:, :64] @ W_dt + b_dt)
    sgemm_kernel<<<dim3(DI / BN, NTOK / BM), blk>>>(
        p_xdbl, NDBL, W_dt, DI, p_delta, DI, 0, NTOK, DI, DTR, DTR, b_dt, 2);

    // 6) selective scan fused with output gating
    scan_kernel<<<dim3(DI / 32, 2), 256>>>(
        p_delta, p_xc, p_xz, p_xdbl, A_log, Dv, p_y);

    // 7) out = y @ W_out                    [4096,2048] x [2048,1024]
    sgemm_kernel<<<dim3(DM / BN, NTOK / BM), blk>>>(
        p_y, DI, W_out, DM, out, DM, 0, NTOK, DM, DI, DI, nullptr, 0);
}

// round 8
// speedup vs baseline: 1.1194x; 1.1194x over previous
#include <cuda_runtime.h>
#include <cuda_bf16.h>
#include <math.h>

// ---------------------------------------------------------------------------
// MambaLayer: B=2, L=2048, D_MODEL=1024, D_INNER=2048, D_STATE=8, D_CONV=4,
// DT_RANK=64.  NTOK = B*L = 4096.
//
//  1) xz    = x @ W_in                         GEMM [4096,1024]x[1024,4096]
//  2) xcpre = causal depthwise conv(x_in)      elementwise
//  3) xc    = silu(xcpre @ pw + conv_bias)     GEMM [4096,2048]x[2048,2048]
//  4) xdbl  = xc @ W_x_pad                     GEMM [4096,2048]x[2048,128] splitK
//  5) delta = softplus(xdbl[:,:64]@W_dt+b_dt)  GEMM [4096,64]x[64,2048]
//  6) selective scan over L (chunked, cp.async double buffered), fused with
//     y = (scan_y + xc*D) * silu(z)
//  7) out   = y @ W_out                        GEMM [4096,2048]x[2048,1024]
// ---------------------------------------------------------------------------

#define NTOK   4096
#define DI     2048
#define DM     1024
#define NDBL   80       // DT_RANK + 2*D_STATE
#define NPAD   128      // padded N for GEMM4
#define DTR    64
#define DST    8
#define NSPLIT 8
#define LSEQ   2048

// ---------------- scratch (device globals: no runtime allocs) --------------
__device__ float g_xz   [(size_t)NTOK * 2 * DI];
__device__ float g_xcpre[(size_t)NTOK * DI];
__device__ float g_xc   [(size_t)NTOK * DI];
__device__ float g_xdbl [(size_t)NTOK * NDBL];
__device__ float g_wxpad[(size_t)DI * NPAD];
__device__ float g_part [(size_t)NSPLIT * NTOK * NPAD];
__device__ float g_delta[(size_t)NTOK * DI];
__device__ float g_y    [(size_t)NTOK * DI];

// ---------------- packed f32x2 helpers -------------------------------------
__device__ __forceinline__ unsigned long long pack2(float lo, float hi) {
    unsigned long long r;
    asm("mov.b64 %0, {%1, %2};" : "=l"(r) : "f"(lo), "f"(hi));
    return r;
}
__device__ __forceinline__ void unpack2(unsigned long long v, float &lo, float &hi) {
    asm("mov.b64 {%0, %1}, %2;" : "=f"(lo), "=f"(hi) : "l"(v));
}
__device__ __forceinline__ void ffma2(unsigned long long &d,
                                      unsigned long long a,
                                      unsigned long long b) {
    // d = a*b + d on two packed fp32 lanes (FFMA2: full-rate fp32 on sm_103a)
    asm("fma.rn.f32x2 %0, %1, %2, %0;" : "+l"(d) : "l"(a), "l"(b));
}

__device__ __forceinline__ void cp16(void* s, const void* g) {
    unsigned saddr = (unsigned)__cvta_generic_to_shared(s);
    asm volatile("cp.async.ca.shared.global [%0], [%1], 16;" :: "r"(saddr), "l"(g));
}

__device__ __forceinline__ float apply_epi(float x, int epi) {
    if (epi == 1) return x / (1.f + expf(-x));                  // silu
    if (epi == 2) return (x > 20.f) ? x : log1pf(expf(x));      // softplus
    return x;
}

// ---------------- generic tiled SGEMM (row-major) --------------------------
// C[M,N] = A[M,K] * B[K,N], N multiple of 128.  Optional bias+activation.
// Optional split-K via grid.z: each z computes K-range [z*kChunk, ...) and
// writes to C + z*zstride (partials reduced later, deterministic).
#define BM 128
#define BN 128
#define BK 16

__global__ __launch_bounds__(256, 2)
void sgemm_kernel(const float* __restrict__ A, int lda,
                  const float* __restrict__ B, int ldb,
                  float* __restrict__ C, int ldc, long long zstride,
                  int M, int N, int K, int kChunk,
                  const float* __restrict__ bias, int epi)
{
    __shared__ float As[BK][BM + 4];
    __shared__ float Bs[BK][BN];

    const int tid = threadIdx.x;
    const int ty = tid >> 4;          // 0..15
    const int tx = tid & 15;          // 0..15
    const int m0 = blockIdx.y * BM;
    const int n0 = blockIdx.x * BN;
    const int k0 = blockIdx.z * kChunk;
    const int k1 = (k0 + kChunk < K) ? (k0 + kChunk) : K;
    C += (long long)blockIdx.z * zstride;

    // A tile: 128 rows x 16 cols = 512 float4; this thread handles q=tid, tid+256
    const int a_r0 = tid >> 2,          a_c0 = (tid & 3) << 2;
    const int a_r1 = (tid + 256) >> 2,  a_c1 = ((tid + 256) & 3) << 2;
    // B tile: 16 rows x 128 cols = 512 float4
    const int b_r0 = tid >> 5,          b_c0 = (tid & 31) << 2;
    const int b_r1 = (tid + 256) >> 5,  b_c1 = ((tid + 256) & 31) << 2;

    float4 avA, avB, bvA, bvB;

    unsigned long long acc[8][4];
#pragma unroll
    for (int i = 0; i < 8; ++i)
#pragma unroll
        for (int j = 0; j < 4; ++j) acc[i][j] = 0ull;

#define LOAD_TILE(kb) do {                                                       \
    avA = *(const float4*)&A[(size_t)(m0 + a_r0) * lda + (kb) + a_c0];           \
    avB = *(const float4*)&A[(size_t)(m0 + a_r1) * lda + (kb) + a_c1];           \
    bvA = *(const float4*)&B[(size_t)((kb) + b_r0) * ldb + n0 + b_c0];           \
    bvB = *(const float4*)&B[(size_t)((kb) + b_r1) * ldb + n0 + b_c1];           \
    } while (0)

#define STORE_TILE() do {                                                        \
    As[a_c0 + 0][a_r0] = avA.x; As[a_c0 + 1][a_r0] = avA.y;                      \
    As[a_c0 + 2][a_r0] = avA.z; As[a_c0 + 3][a_r0] = avA.w;                      \
    As[a_c1 + 0][a_r1] = avB.x; As[a_c1 + 1][a_r1] = avB.y;                      \
    As[a_c1 + 2][a_r1] = avB.z; As[a_c1 + 3][a_r1] = avB.w;                      \
    *(float4*)&Bs[b_r0][b_c0] = bvA;                                             \
    *(float4*)&Bs[b_r1][b_c1] = bvB;                                             \
    } while (0)

    LOAD_TILE(k0);
    STORE_TILE();
    __syncthreads();

    for (int kb = k0; kb < k1; kb += BK) {
        const bool more = (kb + BK < k1);
        if (more) LOAD_TILE(kb + BK);

#pragma unroll
        for (int kk = 0; kk < BK; ++kk) {
            float4 a0 = *(const float4*)&As[kk][ty * 8];
            float4 a1 = *(const float4*)&As[kk][ty * 8 + 4];
            const unsigned long long* bp =
                (const unsigned long long*)&Bs[kk][tx * 8];
            unsigned long long b0 = bp[0], b1 = bp[1], b2 = bp[2], b3 = bp[3];
            float ar[8] = {a0.x, a0.y, a0.z, a0.w, a1.x, a1.y, a1.z, a1.w};
#pragma unroll
            for (int i = 0; i < 8; ++i) {
                unsigned long long aa = pack2(ar[i], ar[i]);
                ffma2(acc[i][0], aa, b0);
                ffma2(acc[i][1], aa, b1);
                ffma2(acc[i][2], aa, b2);
                ffma2(acc[i][3], aa, b3);
            }
        }
        __syncthreads();
        if (more) { STORE_TILE(); __syncthreads(); }
    }

    // epilogue
    const int cbase = n0 + tx * 8;
#pragma unroll
    for (int i = 0; i < 8; ++i) {
        const int row = m0 + ty * 8 + i;
        float v[8];
#pragma unroll
        for (int j = 0; j < 4; ++j) unpack2(acc[i][j], v[2 * j], v[2 * j + 1]);
#pragma unroll
        for (int t = 0; t < 8; ++t) {
            float xv = v[t];
            if (bias) xv += bias[cbase + t];
            v[t] = apply_epi(xv, epi);
        }
        *(float4*)&C[(size_t)row * ldc + cbase]     = make_float4(v[0], v[1], v[2], v[3]);
        *(float4*)&C[(size_t)row * ldc + cbase + 4] = make_float4(v[4], v[5], v[6], v[7]);
    }
#undef LOAD_TILE
#undef STORE_TILE
}

// ---------------- W_x pad: [2048,80] -> [2048,128] (zero-filled) ------------
__global__ void padwx_kernel(const float* __restrict__ wx,
                             float* __restrict__ wp)
{
    int i = blockIdx.x * blockDim.x + threadIdx.x;
    if (i < DI * NPAD) {
        int r = i >> 7, c = i & (NPAD - 1);
        wp[i] = (c < NDBL) ? wx[r * NDBL + c] : 0.f;
    }
}

// ---------------- split-K partial reduce (padded -> compact) ----------------
__global__ void reduce_kernel(const float* __restrict__ part,
                              float* __restrict__ out)
{
    int i = blockIdx.x * blockDim.x + threadIdx.x;
    if (i < NTOK * NDBL) {
        int row = i / NDBL, col = i - row * NDBL;
        float s = 0.f;
#pragma unroll
        for (int z = 0; z < NSPLIT; ++z)
            s += part[(size_t)z * NTOK * NPAD + (size_t)row * NPAD + col];
        out[i] = s;
    }
}

// ---------------- causal depthwise conv (D_CONV=4) ---------------------------
// xz layout [t, 4096]: cols 0..2047 = x_in.  out[t,c] = sum_j x_in[t-3+j,c]*dw[j,c]
__global__ __launch_bounds__(256)
void dwconv_kernel(const float* __restrict__ xz,
                   const float* __restrict__ dw,
                   float* __restrict__ out)
{
    int i = blockIdx.x * blockDim.x + threadIdx.x;   // float4 index
    int c = (i & (DI / 4 - 1)) << 2;
    int t = i >> 9;                                   // DI/4 = 512
    int l = t & (LSEQ - 1);
    float4 acc = make_float4(0.f, 0.f, 0.f, 0.f);
#pragma unroll
    for (int j = 0; j < 4; ++j) {
        int lj = l - 3 + j;
        if (lj >= 0) {
            float4 xv = *(const float4*)&xz[(size_t)(t - 3 + j) * 2 * DI + c];
            float4 wv = *(const float4*)&dw[(size_t)j * DI + c];
            acc.x += xv.x * wv.x; acc.y += xv.y * wv.y;
            acc.z += xv.z * wv.z; acc.w += xv.w * wv.w;
        }
    }
    *(float4*)&out[(size_t)t * DI + c] = acc;
}

// ---------------- selective scan (fused epilogue) ---------------------------
// Thread = (channel cl 0..31, state n 0..7).  Block = 32 channels of one batch.
// Chunked over L in 32-step tiles, cp.async double buffered.
__global__ __launch_bounds__(256)
void scan_kernel(const float* __restrict__ delta,
                 const float* __restrict__ xc,
                 const float* __restrict__ xz,
                 const float* __restrict__ xdbl,
                 const float* __restrict__ A_log,
                 const float* __restrict__ Dv,
                 float* __restrict__ y)
{
    __shared__ float sd[2][32][32];
    __shared__ float sx[2][32][32];
    __shared__ float sz[2][32][32];
    __shared__ float sbc[2][32][16];   // [t][0..7]=B, [t][8..15]=C
    __shared__ float sy[32][32];

    const int tid = threadIdx.x;
    const int n   = tid & 7;
    const int cl  = tid >> 3;
    const int c0  = blockIdx.x * 32;
    const int tb  = blockIdx.y * LSEQ;
    const int c   = c0 + cl;

    const float a2 = -expf(A_log[c * DST + n]) * 1.44269504f;   // A * log2(e)
    const float Dc = Dv[c];
    float h = 0.f;

    const int row = tid >> 3;   // 0..31 (t within chunk)
    const int seg = tid & 7;    // 0..7  (16B segment)

    // prefetch chunk 0
    {
        int t = tb + row;
        cp16(&sd[0][row][seg * 4], delta + (size_t)t * DI + c0 + seg * 4);
        cp16(&sx[0][row][seg * 4], xc    + (size_t)t * DI + c0 + seg * 4);
        cp16(&sz[0][row][seg * 4], xz    + (size_t)t * 2 * DI + DI + c0 + seg * 4);
        if (seg < 4)
            cp16(&sbc[0][row][seg * 4], xdbl + (size_t)t * NDBL + DTR + seg * 4);
        asm volatile("cp.async.commit_group;");
    }

    int buf = 0;
    for (int ch = 0; ch < LSEQ / 32; ++ch) {
        if (ch < LSEQ / 32 - 1) {
            int t = tb + (ch + 1) * 32 + row;
            int nb = buf ^ 1;
            cp16(&sd[nb][row][seg * 4], delta + (size_t)t * DI + c0 + seg * 4);
            cp16(&sx[nb][row][seg * 4], xc    + (size_t)t * DI + c0 + seg * 4);
            cp16(&sz[nb][row][seg * 4], xz    + (size_t)t * 2 * DI + DI + c0 + seg * 4);
            if (seg < 4)
                cp16(&sbc[nb][row][seg * 4], xdbl + (size_t)t * NDBL + DTR + seg * 4);
            asm volatile("cp.async.commit_group;");
            asm volatile("cp.async.wait_group 1;");
        } else {
            asm volatile("cp.async.wait_group 0;");
        }
        __syncthreads();

#pragma unroll
        for (int tt = 0; tt < 32; ++tt) {
            float dlt = sd[buf][tt][cl];
            float xcv = sx[buf][tt][cl];
            float dA  = exp2f(dlt * a2);
            float dBu = dlt * sbc[buf][tt][n] * xcv;
            h = fmaf(dA, h, dBu);
            float p = sbc[buf][tt][8 + n] * h;
            p += __shfl_xor_sync(0xffffffffu, p, 1);
            p += __shfl_xor_sync(0xffffffffu, p, 2);
            p += __shfl_xor_sync(0xffffffffu, p, 4);
            if (n == 0) {
                float yv = p + xcv * Dc;
                float zv = sz[buf][tt][cl];
                sy[tt][cl] = yv * (zv / (1.f + expf(-zv)));
            }
        }
        __syncthreads();

        // coalesced flush of the 32x32 y tile
#pragma unroll
        for (int r = 0; r < 4; ++r) {
            int e  = r * 256 + tid;
            int tt = e >> 5, col = e & 31;
            y[(size_t)(tb + ch * 32 + tt) * DI + c0 + col] = sy[tt][col];
        }
        buf ^= 1;
        // sy reuse is protected by next iteration's __syncthreads()
    }
}

// ---------------------------------------------------------------------------
extern "C" void kernel_launch(void* const* d_in, const int* in_sizes, int n_in,
                              void* d_out, int out_size)
{
    const float* x     = (const float*)d_in[0];
    const float* W_in  = (const float*)d_in[1];
    const float* dw    = (const float*)d_in[2];
    const float* pw    = (const float*)d_in[3];
    const float* cb    = (const float*)d_in[4];
    const float* W_x   = (const float*)d_in[5];
    const float* W_dt  = (const float*)d_in[6];
    const float* b_dt  = (const float*)d_in[7];
    const float* A_log = (const float*)d_in[8];
    const float* Dv    = (const float*)d_in[9];
    const float* W_out = (const float*)d_in[10];
    float* out = (float*)d_out;

    // Resolve scratch addresses on EVERY call (no static caching: kernel_launch
    // must behave identically on the correctness call and the capture call).
    float *p_xz, *p_xcpre, *p_xc, *p_xdbl, *p_wxpad, *p_part, *p_delta, *p_y;
    cudaGetSymbolAddress((void**)&p_xz,    g_xz);
    cudaGetSymbolAddress((void**)&p_xcpre, g_xcpre);
    cudaGetSymbolAddress((void**)&p_xc,    g_xc);
    cudaGetSymbolAddress((void**)&p_xdbl,  g_xdbl);
    cudaGetSymbolAddress((void**)&p_wxpad, g_wxpad);
    cudaGetSymbolAddress((void**)&p_part,  g_part);
    cudaGetSymbolAddress((void**)&p_delta, g_delta);
    cudaGetSymbolAddress((void**)&p_y,     g_y);

    dim3 blk(256);

    // 0) pad W_x to [2048, 128]
    padwx_kernel<<<(DI * NPAD + 255) / 256, 256>>>(W_x, p_wxpad);

    // 1) xz = x @ W_in                      [4096,1024] x [1024,4096]
    sgemm_kernel<<<dim3(2 * DI / BN, NTOK / BM), blk>>>(
        x, DM, W_in, 2 * DI, p_xz, 2 * DI, 0, NTOK, 2 * DI, DM, DM, nullptr, 0);

    // 2) depthwise causal conv
    dwconv_kernel<<<(NTOK * DI / 4) / 256, 256>>>(p_xz, dw, p_xcpre);

    // 3) xc = silu(xcpre @ pw + conv_bias)  [4096,2048] x [2048,2048]
    sgemm_kernel<<<dim3(DI / BN, NTOK / BM), blk>>>(
        p_xcpre, DI, pw, DI, p_xc, DI, 0, NTOK, DI, DI, DI, cb, 1);

    // 4) xdbl = xc @ W_x_pad (split-K=8, deterministic partials, fast path)
    sgemm_kernel<<<dim3(1, NTOK / BM, NSPLIT), blk>>>(
        p_xc, DI, p_wxpad, NPAD, p_part, NPAD, (long long)NTOK * NPAD,
        NTOK, NPAD, DI, DI / NSPLIT, nullptr, 0);
    reduce_kernel<<<(NTOK * NDBL + 255) / 256, 256>>>(p_part, p_xdbl);

    // 5) delta = softplus(xdbl[:, :64] @ W_dt + b_dt)
    sgemm_kernel<<<dim3(DI / BN, NTOK / BM), blk>>>(
        p_xdbl, NDBL, W_dt, DI, p_delta, DI, 0, NTOK, DI, DTR, DTR, b_dt, 2);

    // 6) selective scan fused with output gating
    scan_kernel<<<dim3(DI / 32, 2), 256>>>(
        p_delta, p_xc, p_xz, p_xdbl, A_log, Dv, p_y);

    // 7) out = y @ W_out                    [4096,2048] x [2048,1024]
    sgemm_kernel<<<dim3(DM / BN, NTOK / BM), blk>>>(
        p_y, DI, W_out, DM, out, DM, 0, NTOK, DM, DI, DI, nullptr, 0);
}

// round 13
// speedup vs baseline: 1.9507x; 1.7427x over previous
#include <cuda_runtime.h>
#include <cuda_bf16.h>
#include <math.h>
#include <stdint.h>

// ---------------------------------------------------------------------------
// MambaLayer: B=2, L=2048, D_MODEL=1024, D_INNER=2048, D_STATE=8, D_CONV=4,
// DT_RANK=64.  NTOK = B*L = 4096.
//
// Big GEMMs (1,3,7) run on tensor cores via mma.sync (HMMA, base ISA — the
// harness compiles compute_103 PTX where tcgen05 is unavailable) with
// bf16-split fp32 emulation:
//   A = Ah + Al, B = Bh + Bl (bf16 hi + bf16 residual)
//   D = Ah@Bh + Ah@Bl + Al@Bh  (fp32 register accumulation; AlBl ~2^-16 dropped)
// Small GEMMs (4,5) stay on the fp32 FFMA2 path.
// ---------------------------------------------------------------------------

#define NTOK   4096
#define DI     2048
#define DM     1024
#define NDBL   80       // DT_RANK + 2*D_STATE
#define NPAD   128      // padded N for GEMM4
#define DTR    64
#define DST    8
#define NSPLIT 8
#define LSEQ   2048

// ---------------- scratch (device globals: no runtime allocs) --------------
__device__ float g_xz   [(size_t)NTOK * 2 * DI];
__device__ float g_xc   [(size_t)NTOK * DI];
__device__ float g_xdbl [(size_t)NTOK * NDBL];
__device__ float g_wxpad[(size_t)DI * NPAD];
__device__ float g_part [(size_t)NSPLIT * NTOK * NPAD];
__device__ float g_delta[(size_t)NTOK * DI];

// bf16 split buffers
__device__ __nv_bfloat16 g_xh    [(size_t)NTOK * DM];
__device__ __nv_bfloat16 g_xl    [(size_t)NTOK * DM];
__device__ __nv_bfloat16 g_winT_h[(size_t)(2 * DI) * DM];   // [N=4096, K=1024]
__device__ __nv_bfloat16 g_winT_l[(size_t)(2 * DI) * DM];
__device__ __nv_bfloat16 g_xcp_h [(size_t)NTOK * DI];       // conv output (GEMM3 A)
__device__ __nv_bfloat16 g_xcp_l [(size_t)NTOK * DI];
__device__ __nv_bfloat16 g_pwT_h [(size_t)DI * DI];         // [N=2048, K=2048]
__device__ __nv_bfloat16 g_pwT_l [(size_t)DI * DI];
__device__ __nv_bfloat16 g_yh    [(size_t)NTOK * DI];
__device__ __nv_bfloat16 g_yl    [(size_t)NTOK * DI];
__device__ __nv_bfloat16 g_woutT_h[(size_t)DM * DI];        // [N=1024, K=2048]
__device__ __nv_bfloat16 g_woutT_l[(size_t)DM * DI];

// ---------------- small helpers --------------------------------------------
__device__ __forceinline__ unsigned long long pack2(float lo, float hi) {
    unsigned long long r;
    asm("mov.b64 %0, {%1, %2};" : "=l"(r) : "f"(lo), "f"(hi));
    return r;
}
__device__ __forceinline__ void unpack2(unsigned long long v, float &lo, float &hi) {
    asm("mov.b64 {%0, %1}, %2;" : "=f"(lo), "=f"(hi) : "l"(v));
}
__device__ __forceinline__ void ffma2(unsigned long long &d,
                                      unsigned long long a,
                                      unsigned long long b) {
    asm("fma.rn.f32x2 %0, %1, %2, %0;" : "+l"(d) : "l"(a), "l"(b));
}
__device__ __forceinline__ void cp16(void* s, const void* g) {
    unsigned saddr = (unsigned)__cvta_generic_to_shared(s);
    asm volatile("cp.async.ca.shared.global [%0], [%1], 16;" :: "r"(saddr), "l"(g));
}
__device__ __forceinline__ float apply_epi(float x, int epi) {
    if (epi == 1) return x / (1.f + expf(-x));                  // silu
    if (epi == 2) return (x > 20.f) ? x : log1pf(expf(x));      // softplus
    return x;
}

// ---------------- HMMA (mma.sync) bf16-split GEMM ---------------------------
// C[M,N] = A[M,K] @ B^T with BT given as [N,K] (k-major both sides).
// Tile 128x128x32, 256 thr = 8 warps (4 m x 2 n), warp tile 32x64.
// Three K-phases accumulate AhBh + AhBl + AlBh into fp32 register fragments.
#define HTM 128
#define HTN 128
#define HTK 32
#define ASTR 40          // bf16 units per smem row (32 data + 8 pad = 80 B)

#define LDSM4(r0, r1, r2, r3, addr) \
    asm volatile("ldmatrix.sync.aligned.m8n8.x4.shared.b16 {%0,%1,%2,%3}, [%4];" \
        : "=r"(r0), "=r"(r1), "=r"(r2), "=r"(r3) : "r"(addr))

#define MMA16816(c, a, b) \
    asm volatile("mma.sync.aligned.m16n8k16.row.col.f32.bf16.bf16.f32 " \
        "{%0,%1,%2,%3}, {%4,%5,%6,%7}, {%8,%9}, {%0,%1,%2,%3};" \
        : "+f"((c)[0]), "+f"((c)[1]), "+f"((c)[2]), "+f"((c)[3]) \
        : "r"((a)[0]), "r"((a)[1]), "r"((a)[2]), "r"((a)[3]), \
          "r"((b)[0]), "r"((b)[1]))

__global__ __launch_bounds__(256, 2)
void hmma_kernel(const __nv_bfloat16* __restrict__ Ah,
                 const __nv_bfloat16* __restrict__ Al,
                 const __nv_bfloat16* __restrict__ BhT,
                 const __nv_bfloat16* __restrict__ BlT,
                 float* __restrict__ C, int ldc,
                 int M, int N, int K,
                 const float* __restrict__ bias, int epi)
{
    __shared__ __nv_bfloat16 As[2][HTM * ASTR];
    __shared__ __nv_bfloat16 Bs[2][HTN * ASTR];

    const int tid  = threadIdx.x;
    const int wid  = tid >> 5, lane = tid & 31;
    const int wm   = wid & 3, wn = wid >> 2;
    const int m0   = blockIdx.y * HTM;
    const int n0   = blockIdx.x * HTN;

    const __nv_bfloat16* APh[3] = {Ah, Ah, Al};
    const __nv_bfloat16* BPh[3] = {BhT, BlT, BhT};

    const int kb_per  = K / HTK;
    const int kiters  = 3 * kb_per;

    float acc[2][8][4];
#pragma unroll
    for (int i = 0; i < 2; ++i)
#pragma unroll
        for (int j = 0; j < 8; ++j)
#pragma unroll
            for (int t = 0; t < 4; ++t) acc[i][j][t] = 0.f;

    auto issue = [&](int it) {
        int ph = it / kb_per;
        int kb = (it - ph * kb_per) * HTK;
        const __nv_bfloat16* Ap = APh[ph];
        const __nv_bfloat16* Bp = BPh[ph];
        int slot = it & 1;
#pragma unroll
        for (int q = tid; q < 512; q += 256) {
            int row = q >> 2, cc = (q & 3) << 3;      // 8 bf16 = 16B chunk
            cp16(&As[slot][row * ASTR + cc], Ap + (size_t)(m0 + row) * K + kb + cc);
            cp16(&Bs[slot][row * ASTR + cc], Bp + (size_t)(n0 + row) * K + kb + cc);
        }
        asm volatile("cp.async.commit_group;");
    };

    issue(0);
    for (int it = 0; it < kiters; ++it) {
        asm volatile("cp.async.wait_group 0;");
        __syncthreads();
        if (it + 1 < kiters) issue(it + 1);       // overlaps with compute below

        const int slot = it & 1;
        const uint32_t abase = (uint32_t)__cvta_generic_to_shared(&As[slot][0]);
        const uint32_t bbase = (uint32_t)__cvta_generic_to_shared(&Bs[slot][0]);

#pragma unroll
        for (int k16 = 0; k16 < 2; ++k16) {
            uint32_t a[2][4];
#pragma unroll
            for (int mi = 0; mi < 2; ++mi) {
                uint32_t addr = abase +
                    (((uint32_t)(wm * 32 + mi * 16 + (lane & 15))) * ASTR +
                     ((lane >> 4) << 3) + k16 * 16) * 2u;
                LDSM4(a[mi][0], a[mi][1], a[mi][2], a[mi][3], addr);
            }
            uint32_t b[8][2];
#pragma unroll
            for (int nb = 0; nb < 4; ++nb) {
                uint32_t nrow = (uint32_t)(wn * 64 + nb * 16 +
                                           ((lane >> 4) << 3) + (lane & 7));
                uint32_t addr = bbase +
                    (nrow * ASTR + (((lane >> 3) & 1) << 3) + k16 * 16) * 2u;
                uint32_t r0, r1, r2, r3;
                LDSM4(r0, r1, r2, r3, addr);
                b[nb * 2][0] = r0; b[nb * 2][1] = r1;
                b[nb * 2 + 1][0] = r2; b[nb * 2 + 1][1] = r3;
            }
#pragma unroll
            for (int mi = 0; mi < 2; ++mi)
#pragma unroll
                for (int nj = 0; nj < 8; ++nj)
                    MMA16816(acc[mi][nj], a[mi], b[nj]);
        }
        __syncthreads();
    }

    // epilogue: c frag (m16n8): c0,c1 at (row=lane/4, col=2*(lane%4)+{0,1}),
    //           c2,c3 at row+8.
    const int rbase = m0 + wm * 32;
    const int cb0   = n0 + wn * 64 + ((lane & 3) << 1);
#pragma unroll
    for (int mi = 0; mi < 2; ++mi) {
        const int r0 = rbase + mi * 16 + (lane >> 2);
#pragma unroll
        for (int nj = 0; nj < 8; ++nj) {
            const int col = cb0 + nj * 8;
            float b0 = 0.f, b1 = 0.f;
            if (bias) { b0 = bias[col]; b1 = bias[col + 1]; }
            float2 v0, v1;
            v0.x = apply_epi(acc[mi][nj][0] + b0, epi);
            v0.y = apply_epi(acc[mi][nj][1] + b1, epi);
            v1.x = apply_epi(acc[mi][nj][2] + b0, epi);
            v1.y = apply_epi(acc[mi][nj][3] + b1, epi);
            *(float2*)&C[(size_t)r0 * ldc + col]       = v0;
            *(float2*)&C[(size_t)(r0 + 8) * ldc + col] = v1;
        }
    }
}

// ---------------- fp32 tiled SGEMM (small GEMMs 4,5) ------------------------
#define BM 128
#define BN 128
#define BK 16

__global__ __launch_bounds__(256, 2)
void sgemm_kernel(const float* __restrict__ A, int lda,
                  const float* __restrict__ B, int ldb,
                  float* __restrict__ C, int ldc, long long zstride,
                  int M, int N, int K, int kChunk,
                  const float* __restrict__ bias, int epi)
{
    __shared__ float As[BK][BM + 4];
    __shared__ float Bs[BK][BN];

    const int tid = threadIdx.x;
    const int ty = tid >> 4;
    const int tx = tid & 15;
    const int m0 = blockIdx.y * BM;
    const int n0 = blockIdx.x * BN;
    const int k0 = blockIdx.z * kChunk;
    const int k1 = (k0 + kChunk < K) ? (k0 + kChunk) : K;
    C += (long long)blockIdx.z * zstride;

    const int a_r0 = tid >> 2,          a_c0 = (tid & 3) << 2;
    const int a_r1 = (tid + 256) >> 2,  a_c1 = ((tid + 256) & 3) << 2;
    const int b_r0 = tid >> 5,          b_c0 = (tid & 31) << 2;
    const int b_r1 = (tid + 256) >> 5,  b_c1 = ((tid + 256) & 31) << 2;

    float4 avA, avB, bvA, bvB;

    unsigned long long acc[8][4];
#pragma unroll
    for (int i = 0; i < 8; ++i)
#pragma unroll
        for (int j = 0; j < 4; ++j) acc[i][j] = 0ull;

#define LOAD_TILE(kb) do {                                                       \
    avA = *(const float4*)&A[(size_t)(m0 + a_r0) * lda + (kb) + a_c0];           \
    avB = *(const float4*)&A[(size_t)(m0 + a_r1) * lda + (kb) + a_c1];           \
    bvA = *(const float4*)&B[(size_t)((kb) + b_r0) * ldb + n0 + b_c0];           \
    bvB = *(const float4*)&B[(size_t)((kb) + b_r1) * ldb + n0 + b_c1];           \
    } while (0)

#define STORE_TILE() do {                                                        \
    As[a_c0 + 0][a_r0] = avA.x; As[a_c0 + 1][a_r0] = avA.y;                      \
    As[a_c0 + 2][a_r0] = avA.z; As[a_c0 + 3][a_r0] = avA.w;                      \
    As[a_c1 + 0][a_r1] = avB.x; As[a_c1 + 1][a_r1] = avB.y;                      \
    As[a_c1 + 2][a_r1] = avB.z; As[a_c1 + 3][a_r1] = avB.w;                      \
    *(float4*)&Bs[b_r0][b_c0] = bvA;                                             \
    *(float4*)&Bs[b_r1][b_c1] = bvB;                                             \
    } while (0)

    LOAD_TILE(k0);
    STORE_TILE();
    __syncthreads();

    for (int kb = k0; kb < k1; kb += BK) {
        const bool more = (kb + BK < k1);
        if (more) LOAD_TILE(kb + BK);

#pragma unroll
        for (int kk = 0; kk < BK; ++kk) {
            float4 a0 = *(const float4*)&As[kk][ty * 8];
            float4 a1 = *(const float4*)&As[kk][ty * 8 + 4];
            const unsigned long long* bp =
                (const unsigned long long*)&Bs[kk][tx * 8];
            unsigned long long b0 = bp[0], b1 = bp[1], b2 = bp[2], b3 = bp[3];
            float ar[8] = {a0.x, a0.y, a0.z, a0.w, a1.x, a1.y, a1.z, a1.w};
#pragma unroll
            for (int i = 0; i < 8; ++i) {
                unsigned long long aa = pack2(ar[i], ar[i]);
                ffma2(acc[i][0], aa, b0);
                ffma2(acc[i][1], aa, b1);
                ffma2(acc[i][2], aa, b2);
                ffma2(acc[i][3], aa, b3);
            }
        }
        __syncthreads();
        if (more) { STORE_TILE(); __syncthreads(); }
    }

    const int cbase = n0 + tx * 8;
#pragma unroll
    for (int i = 0; i < 8; ++i) {
        const int row = m0 + ty * 8 + i;
        float v[8];
#pragma unroll
        for (int j = 0; j < 4; ++j) unpack2(acc[i][j], v[2 * j], v[2 * j + 1]);
#pragma unroll
        for (int t = 0; t < 8; ++t) {
            float xv = v[t];
            if (bias) xv += bias[cbase + t];
            v[t] = apply_epi(xv, epi);
        }
        *(float4*)&C[(size_t)row * ldc + cbase]     = make_float4(v[0], v[1], v[2], v[3]);
        *(float4*)&C[(size_t)row * ldc + cbase + 4] = make_float4(v[4], v[5], v[6], v[7]);
    }
#undef LOAD_TILE
#undef STORE_TILE
}

// ---------------- conversion kernels ----------------------------------------
__global__ void split_kernel(const float* __restrict__ src,
                             __nv_bfloat16* __restrict__ h,
                             __nv_bfloat16* __restrict__ l, int n)
{
    int i = blockIdx.x * blockDim.x + threadIdx.x;
    if (i < n) {
        float v = src[i];
        __nv_bfloat16 hh = __float2bfloat16(v);
        h[i] = hh;
        l[i] = __float2bfloat16(v - __bfloat162float(hh));
    }
}

// transpose + split: src[K,N] fp32 -> hT,lT [N,K] bf16
__global__ __launch_bounds__(256)
void tsplit_kernel(const float* __restrict__ src, int K, int N,
                   __nv_bfloat16* __restrict__ hT,
                   __nv_bfloat16* __restrict__ lT)
{
    __shared__ float t[32][33];
    const int bx = blockIdx.x * 32;   // N
    const int by = blockIdx.y * 32;   // K
    const int tx = threadIdx.x & 31, ty = threadIdx.x >> 5;   // ty 0..7
#pragma unroll
    for (int j = 0; j < 32; j += 8)
        t[ty + j][tx] = src[(size_t)(by + ty + j) * N + bx + tx];
    __syncthreads();
#pragma unroll
    for (int j = 0; j < 32; j += 8) {
        float v = t[tx][ty + j];
        __nv_bfloat16 hh = __float2bfloat16(v);
        size_t o = (size_t)(bx + ty + j) * K + by + tx;
        hT[o] = hh;
        lT[o] = __float2bfloat16(v - __bfloat162float(hh));
    }
}

// ---------------- W_x pad: [2048,80] -> [2048,128] --------------------------
__global__ void padwx_kernel(const float* __restrict__ wx,
                             float* __restrict__ wp)
{
    int i = blockIdx.x * blockDim.x + threadIdx.x;
    if (i < DI * NPAD) {
        int r = i >> 7, c = i & (NPAD - 1);
        wp[i] = (c < NDBL) ? wx[r * NDBL + c] : 0.f;
    }
}

// ---------------- split-K partial reduce ------------------------------------
__global__ void reduce_kernel(const float* __restrict__ part,
                              float* __restrict__ out)
{
    int i = blockIdx.x * blockDim.x + threadIdx.x;
    if (i < NTOK * NDBL) {
        int row = i / NDBL, col = i - row * NDBL;
        float s = 0.f;
#pragma unroll
        for (int z = 0; z < NSPLIT; ++z)
            s += part[(size_t)z * NTOK * NPAD + (size_t)row * NPAD + col];
        out[i] = s;
    }
}

// ---------------- causal depthwise conv -> bf16 split ------------------------
__global__ __launch_bounds__(256)
void dwconv_kernel(const float* __restrict__ xz,
                   const float* __restrict__ dw,
                   __nv_bfloat16* __restrict__ oh,
                   __nv_bfloat16* __restrict__ ol)
{
    int i = blockIdx.x * blockDim.x + threadIdx.x;   // float4 index
    int c = (i & (DI / 4 - 1)) << 2;
    int t = i >> 9;                                   // DI/4 = 512
    int l = t & (LSEQ - 1);
    float4 acc = make_float4(0.f, 0.f, 0.f, 0.f);
#pragma unroll
    for (int j = 0; j < 4; ++j) {
        int lj = l - 3 + j;
        if (lj >= 0) {
            float4 xv = *(const float4*)&xz[(size_t)(t - 3 + j) * 2 * DI + c];
            float4 wv = *(const float4*)&dw[(size_t)j * DI + c];
            acc.x += xv.x * wv.x; acc.y += xv.y * wv.y;
            acc.z += xv.z * wv.z; acc.w += xv.w * wv.w;
        }
    }
    float vs[4] = {acc.x, acc.y, acc.z, acc.w};
    size_t o = (size_t)t * DI + c;
#pragma unroll
    for (int j = 0; j < 4; ++j) {
        __nv_bfloat16 hh = __float2bfloat16(vs[j]);
        oh[o + j] = hh;
        ol[o + j] = __float2bfloat16(vs[j] - __bfloat162float(hh));
    }
}

// ---------------- selective scan (fused epilogue -> bf16 split y) ------------
__global__ __launch_bounds__(256)
void scan_kernel(const float* __restrict__ delta,
                 const float* __restrict__ xc,
                 const float* __restrict__ xz,
                 const float* __restrict__ xdbl,
                 const float* __restrict__ A_log,
                 const float* __restrict__ Dv,
                 __nv_bfloat16* __restrict__ yh,
                 __nv_bfloat16* __restrict__ yl)
{
    __shared__ float sd[2][32][32];
    __shared__ float sx[2][32][32];
    __shared__ float sz[2][32][32];
    __shared__ float sbc[2][32][16];
    __shared__ float sy[32][32];

    const int tid = threadIdx.x;
    const int n   = tid & 7;
    const int cl  = tid >> 3;
    const int c0  = blockIdx.x * 32;
    const int tb  = blockIdx.y * LSEQ;
    const int c   = c0 + cl;

    const float a2 = -expf(A_log[c * DST + n]) * 1.44269504f;
    const float Dc = Dv[c];
    float h = 0.f;

    const int row = tid >> 3;
    const int seg = tid & 7;

    {
        int t = tb + row;
        cp16(&sd[0][row][seg * 4], delta + (size_t)t * DI + c0 + seg * 4);
        cp16(&sx[0][row][seg * 4], xc    + (size_t)t * DI + c0 + seg * 4);
        cp16(&sz[0][row][seg * 4], xz    + (size_t)t * 2 * DI + DI + c0 + seg * 4);
        if (seg < 4)
            cp16(&sbc[0][row][seg * 4], xdbl + (size_t)t * NDBL + DTR + seg * 4);
        asm volatile("cp.async.commit_group;");
    }

    int buf = 0;
    for (int ch = 0; ch < LSEQ / 32; ++ch) {
        if (ch < LSEQ / 32 - 1) {
            int t = tb + (ch + 1) * 32 + row;
            int nb = buf ^ 1;
            cp16(&sd[nb][row][seg * 4], delta + (size_t)t * DI + c0 + seg * 4);
            cp16(&sx[nb][row][seg * 4], xc    + (size_t)t * DI + c0 + seg * 4);
            cp16(&sz[nb][row][seg * 4], xz    + (size_t)t * 2 * DI + DI + c0 + seg * 4);
            if (seg < 4)
                cp16(&sbc[nb][row][seg * 4], xdbl + (size_t)t * NDBL + DTR + seg * 4);
            asm volatile("cp.async.commit_group;");
            asm volatile("cp.async.wait_group 1;");
        } else {
            asm volatile("cp.async.wait_group 0;");
        }
        __syncthreads();

#pragma unroll
        for (int tt = 0; tt < 32; ++tt) {
            float dlt = sd[buf][tt][cl];
            float xcv = sx[buf][tt][cl];
            float dA  = exp2f(dlt * a2);
            float dBu = dlt * sbc[buf][tt][n] * xcv;
            h = fmaf(dA, h, dBu);
            float p = sbc[buf][tt][8 + n] * h;
            p += __shfl_xor_sync(0xffffffffu, p, 1);
            p += __shfl_xor_sync(0xffffffffu, p, 2);
            p += __shfl_xor_sync(0xffffffffu, p, 4);
            if (n == 0) {
                float yv = p + xcv * Dc;
                float zv = sz[buf][tt][cl];
                sy[tt][cl] = yv * (zv / (1.f + expf(-zv)));
            }
        }
        __syncthreads();

#pragma unroll
        for (int r = 0; r < 4; ++r) {
            int e  = r * 256 + tid;
            int tt = e >> 5, col = e & 31;
            float v = sy[tt][col];
            __nv_bfloat16 hh = __float2bfloat16(v);
            size_t o = (size_t)(tb + ch * 32 + tt) * DI + c0 + col;
            yh[o] = hh;
            yl[o] = __float2bfloat16(v - __bfloat162float(hh));
        }
        buf ^= 1;
    }
}

// ---------------------------------------------------------------------------
extern "C" void kernel_launch(void* const* d_in, const int* in_sizes, int n_in,
                              void* d_out, int out_size)
{
    const float* x     = (const float*)d_in[0];
    const float* W_in  = (const float*)d_in[1];
    const float* dw    = (const float*)d_in[2];
    const float* pw    = (const float*)d_in[3];
    const float* cb    = (const float*)d_in[4];
    const float* W_x   = (const float*)d_in[5];
    const float* W_dt  = (const float*)d_in[6];
    const float* b_dt  = (const float*)d_in[7];
    const float* A_log = (const float*)d_in[8];
    const float* Dv    = (const float*)d_in[9];
    const float* W_out = (const float*)d_in[10];
    float* out = (float*)d_out;

    // Resolve scratch addresses on EVERY call (capture-identical behavior).
    float *p_xz, *p_xc, *p_xdbl, *p_wxpad, *p_part, *p_delta;
    __nv_bfloat16 *p_xh, *p_xl, *p_winh, *p_winl, *p_xcph, *p_xcpl;
    __nv_bfloat16 *p_pwh, *p_pwl, *p_yh, *p_yl, *p_woh, *p_wol;
    cudaGetSymbolAddress((void**)&p_xz,    g_xz);
    cudaGetSymbolAddress((void**)&p_xc,    g_xc);
    cudaGetSymbolAddress((void**)&p_xdbl,  g_xdbl);
    cudaGetSymbolAddress((void**)&p_wxpad, g_wxpad);
    cudaGetSymbolAddress((void**)&p_part,  g_part);
    cudaGetSymbolAddress((void**)&p_delta, g_delta);
    cudaGetSymbolAddress((void**)&p_xh,    g_xh);
    cudaGetSymbolAddress((void**)&p_xl,    g_xl);
    cudaGetSymbolAddress((void**)&p_winh,  g_winT_h);
    cudaGetSymbolAddress((void**)&p_winl,  g_winT_l);
    cudaGetSymbolAddress((void**)&p_xcph,  g_xcp_h);
    cudaGetSymbolAddress((void**)&p_xcpl,  g_xcp_l);
    cudaGetSymbolAddress((void**)&p_pwh,   g_pwT_h);
    cudaGetSymbolAddress((void**)&p_pwl,   g_pwT_l);
    cudaGetSymbolAddress((void**)&p_yh,    g_yh);
    cudaGetSymbolAddress((void**)&p_yl,    g_yl);
    cudaGetSymbolAddress((void**)&p_woh,   g_woutT_h);
    cudaGetSymbolAddress((void**)&p_wol,   g_woutT_l);

    // weight preprocessing
    tsplit_kernel<<<dim3(2 * DI / 32, DM / 32), 256>>>(W_in, DM, 2 * DI, p_winh, p_winl);
    tsplit_kernel<<<dim3(DI / 32, DI / 32), 256>>>(pw, DI, DI, p_pwh, p_pwl);
    tsplit_kernel<<<dim3(DM / 32, DI / 32), 256>>>(W_out, DI, DM, p_woh, p_wol);
    split_kernel<<<(NTOK * DM + 255) / 256, 256>>>(x, p_xh, p_xl, NTOK * DM);
    padwx_kernel<<<(DI * NPAD + 255) / 256, 256>>>(W_x, p_wxpad);

    // 1) xz = x @ W_in    (HMMA bf16-split)
    hmma_kernel<<<dim3(2 * DI / HTN, NTOK / HTM), 256>>>(
        p_xh, p_xl, p_winh, p_winl, p_xz, 2 * DI, NTOK, 2 * DI, DM, nullptr, 0);

    // 2) depthwise causal conv (emits bf16 split directly)
    dwconv_kernel<<<(NTOK * DI / 4) / 256, 256>>>(p_xz, dw, p_xcph, p_xcpl);

    // 3) xc = silu(conv @ pw + cb)   (HMMA bf16-split)
    hmma_kernel<<<dim3(DI / HTN, NTOK / HTM), 256>>>(
        p_xcph, p_xcpl, p_pwh, p_pwl, p_xc, DI, NTOK, DI, DI, cb, 1);

    // 4) xdbl = xc @ W_x_pad (fp32 split-K, deterministic)
    sgemm_kernel<<<dim3(1, NTOK / BM, NSPLIT), 256>>>(
        p_xc, DI, p_wxpad, NPAD, p_part, NPAD, (long long)NTOK * NPAD,
        NTOK, NPAD, DI, DI / NSPLIT, nullptr, 0);
    reduce_kernel<<<(NTOK * NDBL + 255) / 256, 256>>>(p_part, p_xdbl);

    // 5) delta = softplus(xdbl[:, :64] @ W_dt + b_dt)  (fp32)
    sgemm_kernel<<<dim3(DI / BN, NTOK / BM), 256>>>(
        p_xdbl, NDBL, W_dt, DI, p_delta, DI, 0, NTOK, DI, DTR, DTR, b_dt, 2);

    // 6) selective scan fused with gating (emits bf16 split y)
    scan_kernel<<<dim3(DI / 32, 2), 256>>>(
        p_delta, p_xc, p_xz, p_xdbl, A_log, Dv, p_yh, p_yl);

    // 7) out = y @ W_out   (HMMA bf16-split)
    hmma_kernel<<<dim3(DM / HTN, NTOK / HTM), 256>>>(
        p_yh, p_yl, p_woh, p_wol, out, DM, NTOK, DM, DI, nullptr, 0);
}

// round 16
// speedup vs baseline: 2.1724x; 1.1136x over previous
#include <cuda_runtime.h>
#include <cuda_bf16.h>
#include <math.h>
#include <stdint.h>

// ---------------------------------------------------------------------------
// MambaLayer: B=2, L=2048, D_MODEL=1024, D_INNER=2048, D_STATE=8, D_CONV=4,
// DT_RANK=64.  NTOK = B*L = 4096.
//
// Big GEMMs (1,3,7) on tensor cores via mma.sync (HMMA base ISA) with
// bf16-split fp32 emulation:
//   A = Ah + Al, B = Bh + Bl  ->  D = AhBh + AhBl + AlBh (fp32 reg acc)
// Merged-phase mainloop: all 4 tiles (Ah,Al,Bh,Bl) staged ONCE per K-block,
// 3 MMA products issued from resident smem (vs 3 separate staging phases).
// ---------------------------------------------------------------------------

#define NTOK   4096
#define DI     2048
#define DM     1024
#define NDBL   80       // DT_RANK + 2*D_STATE
#define NPAD   128      // padded N for GEMM4
#define DTR    64
#define DST    8
#define NSPLIT 8
#define LSEQ   2048

// ---------------- scratch (device globals: no runtime allocs) --------------
__device__ float g_xz   [(size_t)NTOK * 2 * DI];
__device__ float g_xc   [(size_t)NTOK * DI];
__device__ float g_xdbl [(size_t)NTOK * NDBL];
__device__ float g_wxpad[(size_t)DI * NPAD];
__device__ float g_part [(size_t)NSPLIT * NTOK * NPAD];
__device__ float g_delta[(size_t)NTOK * DI];

// bf16 split buffers
__device__ __nv_bfloat16 g_xh    [(size_t)NTOK * DM];
__device__ __nv_bfloat16 g_xl    [(size_t)NTOK * DM];
__device__ __nv_bfloat16 g_winT_h[(size_t)(2 * DI) * DM];   // [N=4096, K=1024]
__device__ __nv_bfloat16 g_winT_l[(size_t)(2 * DI) * DM];
__device__ __nv_bfloat16 g_xcp_h [(size_t)NTOK * DI];
__device__ __nv_bfloat16 g_xcp_l [(size_t)NTOK * DI];
__device__ __nv_bfloat16 g_pwT_h [(size_t)DI * DI];         // [N=2048, K=2048]
__device__ __nv_bfloat16 g_pwT_l [(size_t)DI * DI];
__device__ __nv_bfloat16 g_yh    [(size_t)NTOK * DI];
__device__ __nv_bfloat16 g_yl    [(size_t)NTOK * DI];
__device__ __nv_bfloat16 g_woutT_h[(size_t)DM * DI];        // [N=1024, K=2048]
__device__ __nv_bfloat16 g_woutT_l[(size_t)DM * DI];

// ---------------- small helpers --------------------------------------------
__device__ __forceinline__ unsigned long long pack2(float lo, float hi) {
    unsigned long long r;
    asm("mov.b64 %0, {%1, %2};" : "=l"(r) : "f"(lo), "f"(hi));
    return r;
}
__device__ __forceinline__ void unpack2(unsigned long long v, float &lo, float &hi) {
    asm("mov.b64 {%0, %1}, %2;" : "=f"(lo), "=f"(hi) : "l"(v));
}
__device__ __forceinline__ void ffma2(unsigned long long &d,
                                      unsigned long long a,
                                      unsigned long long b) {
    asm("fma.rn.f32x2 %0, %1, %2, %0;" : "+l"(d) : "l"(a), "l"(b));
}
__device__ __forceinline__ void cp16(void* s, const void* g) {
    unsigned saddr = (unsigned)__cvta_generic_to_shared(s);
    asm volatile("cp.async.ca.shared.global [%0], [%1], 16;" :: "r"(saddr), "l"(g));
}
__device__ __forceinline__ float apply_epi(float x, int epi) {
    if (epi == 1) return x / (1.f + expf(-x));                  // silu
    if (epi == 2) return (x > 20.f) ? x : log1pf(expf(x));      // softplus
    return x;
}

// ---------------- HMMA (mma.sync) bf16-split GEMM, merged phases ------------
// C[M,N] = A[M,K] @ B^T with BT given as [N,K] (k-major both sides).
// Tile 128x128x32, 256 thr = 8 warps (4 m x 2 n), warp tile 32x64.
#define HTM 128
#define HTN 128
#define HTK 32
#define ASTR 40            // bf16 per smem row (32 data + 8 pad = 80 B)
#define TILEE (HTM * ASTR) // 5120 bf16 = 10240 B per tile
#define HSME  (2 * 4 * TILEE)            // elements: 2 stages x 4 tiles
#define HSMB  (HSME * 2)                 // 81920 bytes dynamic smem

#define LDSM4(r0, r1, r2, r3, addr) \
    asm volatile("ldmatrix.sync.aligned.m8n8.x4.shared.b16 {%0,%1,%2,%3}, [%4];" \
        : "=r"(r0), "=r"(r1), "=r"(r2), "=r"(r3) : "r"(addr))

#define MMA16816(c, a, b) \
    asm volatile("mma.sync.aligned.m16n8k16.row.col.f32.bf16.bf16.f32 " \
        "{%0,%1,%2,%3}, {%4,%5,%6,%7}, {%8,%9}, {%0,%1,%2,%3};" \
        : "+f"((c)[0]), "+f"((c)[1]), "+f"((c)[2]), "+f"((c)[3]) \
        : "r"((a)[0]), "r"((a)[1]), "r"((a)[2]), "r"((a)[3]), \
          "r"((b)[0]), "r"((b)[1]))

__global__ __launch_bounds__(256, 2)
void hmma_kernel(const __nv_bfloat16* __restrict__ Ah,
                 const __nv_bfloat16* __restrict__ Al,
                 const __nv_bfloat16* __restrict__ BhT,
                 const __nv_bfloat16* __restrict__ BlT,
                 float* __restrict__ C, int ldc,
                 int M, int N, int K,
                 const float* __restrict__ bias, int epi)
{
    extern __shared__ __nv_bfloat16 sm[];

    const int tid  = threadIdx.x;
    const int wid  = tid >> 5, lane = tid & 31;
    const int wm   = wid & 3, wn = wid >> 2;
    const int m0   = blockIdx.y * HTM;
    const int n0   = blockIdx.x * HTN;

    const int kiters = K / HTK;

    float acc[2][8][4];
#pragma unroll
    for (int i = 0; i < 2; ++i)
#pragma unroll
        for (int j = 0; j < 8; ++j)
#pragma unroll
            for (int t = 0; t < 4; ++t) acc[i][j][t] = 0.f;

    auto issue = [&](int it) {
        const int kb = it * HTK;
        __nv_bfloat16* st = sm + (it & 1) * 4 * TILEE;
#pragma unroll
        for (int q = tid; q < 512; q += 256) {
            const int row = q >> 2, cc = (q & 3) << 3;   // 8 bf16 = 16B chunk
            const size_t ga = (size_t)(m0 + row) * K + kb + cc;
            const size_t gb = (size_t)(n0 + row) * K + kb + cc;
            const int so = row * ASTR + cc;
            cp16(st + so,             Ah  + ga);
            cp16(st + TILEE + so,     Al  + ga);
            cp16(st + 2 * TILEE + so, BhT + gb);
            cp16(st + 3 * TILEE + so, BlT + gb);
        }
        asm volatile("cp.async.commit_group;");
    };

    issue(0);
    for (int it = 0; it < kiters; ++it) {
        asm volatile("cp.async.wait_group 0;");
        __syncthreads();
        if (it + 1 < kiters) issue(it + 1);   // overlaps with compute below

        __nv_bfloat16* st = sm + (it & 1) * 4 * TILEE;
        const uint32_t ah_b = (uint32_t)__cvta_generic_to_shared(st);
        const uint32_t al_b = ah_b + TILEE * 2u;
        const uint32_t bh_b = ah_b + 2u * TILEE * 2u;
        const uint32_t bl_b = ah_b + 3u * TILEE * 2u;

#pragma unroll
        for (int k16 = 0; k16 < 2; ++k16) {
            const uint32_t aoff =
                (((uint32_t)(wm * 32 + (lane & 15))) * ASTR +
                 ((lane >> 4) << 3) + k16 * 16) * 2u;
            const uint32_t boff0 =
                (((uint32_t)(wn * 64 + ((lane >> 4) << 3) + (lane & 7))) * ASTR +
                 (((lane >> 3) & 1) << 3) + k16 * 16) * 2u;

            uint32_t a1[2][4], a2[2][4], bb[8][2];
            // --- ah, bh ---
#pragma unroll
            for (int mi = 0; mi < 2; ++mi)
                LDSM4(a1[mi][0], a1[mi][1], a1[mi][2], a1[mi][3],
                      ah_b + aoff + (uint32_t)(mi * 16 * ASTR) * 2u);
#pragma unroll
            for (int nb = 0; nb < 4; ++nb) {
                uint32_t r0, r1, r2, r3;
                LDSM4(r0, r1, r2, r3,
                      bh_b + boff0 + (uint32_t)(nb * 16 * ASTR) * 2u);
                bb[nb * 2][0] = r0;     bb[nb * 2][1] = r1;
                bb[nb * 2 + 1][0] = r2; bb[nb * 2 + 1][1] = r3;
            }
#pragma unroll
            for (int mi = 0; mi < 2; ++mi)
#pragma unroll
                for (int nj = 0; nj < 8; ++nj)
                    MMA16816(acc[mi][nj], a1[mi], bb[nj]);
            // --- al x bh ---
#pragma unroll
            for (int mi = 0; mi < 2; ++mi)
                LDSM4(a2[mi][0], a2[mi][1], a2[mi][2], a2[mi][3],
                      al_b + aoff + (uint32_t)(mi * 16 * ASTR) * 2u);
#pragma unroll
            for (int mi = 0; mi < 2; ++mi)
#pragma unroll
                for (int nj = 0; nj < 8; ++nj)
                    MMA16816(acc[mi][nj], a2[mi], bb[nj]);
            // --- ah x bl (bl overwrites bh frags) ---
#pragma unroll
            for (int nb = 0; nb < 4; ++nb) {
                uint32_t r0, r1, r2, r3;
                LDSM4(r0, r1, r2, r3,
                      bl_b + boff0 + (uint32_t)(nb * 16 * ASTR) * 2u);
                bb[nb * 2][0] = r0;     bb[nb * 2][1] = r1;
                bb[nb * 2 + 1][0] = r2; bb[nb * 2 + 1][1] = r3;
            }
#pragma unroll
            for (int mi = 0; mi < 2; ++mi)
#pragma unroll
                for (int nj = 0; nj < 8; ++nj)
                    MMA16816(acc[mi][nj], a1[mi], bb[nj]);
        }
        __syncthreads();
    }

    // epilogue: c frag (m16n8): c0,c1 at (row=lane/4, col=2*(lane%4)+{0,1}),
    //           c2,c3 at row+8.
    const int rbase = m0 + wm * 32;
    const int cb0   = n0 + wn * 64 + ((lane & 3) << 1);
#pragma unroll
    for (int mi = 0; mi < 2; ++mi) {
        const int r0 = rbase + mi * 16 + (lane >> 2);
#pragma unroll
        for (int nj = 0; nj < 8; ++nj) {
            const int col = cb0 + nj * 8;
            float b0 = 0.f, b1 = 0.f;
            if (bias) { b0 = bias[col]; b1 = bias[col + 1]; }
            float2 v0, v1;
            v0.x = apply_epi(acc[mi][nj][0] + b0, epi);
            v0.y = apply_epi(acc[mi][nj][1] + b1, epi);
            v1.x = apply_epi(acc[mi][nj][2] + b0, epi);
            v1.y = apply_epi(acc[mi][nj][3] + b1, epi);
            *(float2*)&C[(size_t)r0 * ldc + col]       = v0;
            *(float2*)&C[(size_t)(r0 + 8) * ldc + col] = v1;
        }
    }
}

// ---------------- fp32 tiled SGEMM (small GEMMs 4,5) ------------------------
#define BM 128
#define BN 128
#define BK 16

__global__ __launch_bounds__(256, 2)
void sgemm_kernel(const float* __restrict__ A, int lda,
                  const float* __restrict__ B, int ldb,
                  float* __restrict__ C, int ldc, long long zstride,
                  int M, int N, int K, int kChunk,
                  const float* __restrict__ bias, int epi)
{
    __shared__ float As[BK][BM + 4];
    __shared__ float Bs[BK][BN];

    const int tid = threadIdx.x;
    const int ty = tid >> 4;
    const int tx = tid & 15;
    const int m0 = blockIdx.y * BM;
    const int n0 = blockIdx.x * BN;
    const int k0 = blockIdx.z * kChunk;
    const int k1 = (k0 + kChunk < K) ? (k0 + kChunk) : K;
    C += (long long)blockIdx.z * zstride;

    const int a_r0 = tid >> 2,          a_c0 = (tid & 3) << 2;
    const int a_r1 = (tid + 256) >> 2,  a_c1 = ((tid + 256) & 3) << 2;
    const int b_r0 = tid >> 5,          b_c0 = (tid & 31) << 2;
    const int b_r1 = (tid + 256) >> 5,  b_c1 = ((tid + 256) & 31) << 2;

    float4 avA, avB, bvA, bvB;

    unsigned long long acc[8][4];
#pragma unroll
    for (int i = 0; i < 8; ++i)
#pragma unroll
        for (int j = 0; j < 4; ++j) acc[i][j] = 0ull;

#define LOAD_TILE(kb) do {                                                       \
    avA = *(const float4*)&A[(size_t)(m0 + a_r0) * lda + (kb) + a_c0];           \
    avB = *(const float4*)&A[(size_t)(m0 + a_r1) * lda + (kb) + a_c1];           \
    bvA = *(const float4*)&B[(size_t)((kb) + b_r0) * ldb + n0 + b_c0];           \
    bvB = *(const float4*)&B[(size_t)((kb) + b_r1) * ldb + n0 + b_c1];           \
    } while (0)

#define STORE_TILE() do {                                                        \
    As[a_c0 + 0][a_r0] = avA.x; As[a_c0 + 1][a_r0] = avA.y;                      \
    As[a_c0 + 2][a_r0] = avA.z; As[a_c0 + 3][a_r0] = avA.w;                      \
    As[a_c1 + 0][a_r1] = avB.x; As[a_c1 + 1][a_r1] = avB.y;                      \
    As[a_c1 + 2][a_r1] = avB.z; As[a_c1 + 3][a_r1] = avB.w;                      \
    *(float4*)&Bs[b_r0][b_c0] = bvA;                                             \
    *(float4*)&Bs[b_r1][b_c1] = bvB;                                             \
    } while (0)

    LOAD_TILE(k0);
    STORE_TILE();
    __syncthreads();

    for (int kb = k0; kb < k1; kb += BK) {
        const bool more = (kb + BK < k1);
        if (more) LOAD_TILE(kb + BK);

#pragma unroll
        for (int kk = 0; kk < BK; ++kk) {
            float4 a0 = *(const float4*)&As[kk][ty * 8];
            float4 a1 = *(const float4*)&As[kk][ty * 8 + 4];
            const unsigned long long* bp =
                (const unsigned long long*)&Bs[kk][tx * 8];
            unsigned long long b0 = bp[0], b1 = bp[1], b2 = bp[2], b3 = bp[3];
            float ar[8] = {a0.x, a0.y, a0.z, a0.w, a1.x, a1.y, a1.z, a1.w};
#pragma unroll
            for (int i = 0; i < 8; ++i) {
                unsigned long long aa = pack2(ar[i], ar[i]);
                ffma2(acc[i][0], aa, b0);
                ffma2(acc[i][1], aa, b1);
                ffma2(acc[i][2], aa, b2);
                ffma2(acc[i][3], aa, b3);
            }
        }
        __syncthreads();
        if (more) { STORE_TILE(); __syncthreads(); }
    }

    const int cbase = n0 + tx * 8;
#pragma unroll
    for (int i = 0; i < 8; ++i) {
        const int row = m0 + ty * 8 + i;
        float v[8];
#pragma unroll
        for (int j = 0; j < 4; ++j) unpack2(acc[i][j], v[2 * j], v[2 * j + 1]);
#pragma unroll
        for (int t = 0; t < 8; ++t) {
            float xv = v[t];
            if (bias) xv += bias[cbase + t];
            v[t] = apply_epi(xv, epi);
        }
        *(float4*)&C[(size_t)row * ldc + cbase]     = make_float4(v[0], v[1], v[2], v[3]);
        *(float4*)&C[(size_t)row * ldc + cbase + 4] = make_float4(v[4], v[5], v[6], v[7]);
    }
#undef LOAD_TILE
#undef STORE_TILE
}

// ---------------- conversion kernels ----------------------------------------
__global__ void split_kernel(const float* __restrict__ src,
                             __nv_bfloat16* __restrict__ h,
                             __nv_bfloat16* __restrict__ l, int n)
{
    int i = blockIdx.x * blockDim.x + threadIdx.x;      // float4 index
    if (i * 4 < n) {
        float4 v = *(const float4*)&src[i * 4];
        float vs[4] = {v.x, v.y, v.z, v.w};
        __nv_bfloat16 hh[4], ll[4];
#pragma unroll
        for (int j = 0; j < 4; ++j) {
            hh[j] = __float2bfloat16(vs[j]);
            ll[j] = __float2bfloat16(vs[j] - __bfloat162float(hh[j]));
        }
        *(uint2*)&h[i * 4] = *(uint2*)hh;
        *(uint2*)&l[i * 4] = *(uint2*)ll;
    }
}

// transpose + split: src[K,N] fp32 -> hT,lT [N,K] bf16
__global__ __launch_bounds__(256)
void tsplit_kernel(const float* __restrict__ src, int K, int N,
                   __nv_bfloat16* __restrict__ hT,
                   __nv_bfloat16* __restrict__ lT)
{
    __shared__ float t[32][33];
    const int bx = blockIdx.x * 32;   // N
    const int by = blockIdx.y * 32;   // K
    const int tx = threadIdx.x & 31, ty = threadIdx.x >> 5;   // ty 0..7
#pragma unroll
    for (int j = 0; j < 32; j += 8)
        t[ty + j][tx] = src[(size_t)(by + ty + j) * N + bx + tx];
    __syncthreads();
#pragma unroll
    for (int j = 0; j < 32; j += 8) {
        float v = t[tx][ty + j];
        __nv_bfloat16 hh = __float2bfloat16(v);
        size_t o = (size_t)(bx + ty + j) * K + by + tx;
        hT[o] = hh;
        lT[o] = __float2bfloat16(v - __bfloat162float(hh));
    }
}

// ---------------- W_x pad: [2048,80] -> [2048,128] --------------------------
__global__ void padwx_kernel(const float* __restrict__ wx,
                             float* __restrict__ wp)
{
    int i = blockIdx.x * blockDim.x + threadIdx.x;
    if (i < DI * NPAD) {
        int r = i >> 7, c = i & (NPAD - 1);
        wp[i] = (c < NDBL) ? wx[r * NDBL + c] : 0.f;
    }
}

// ---------------- split-K partial reduce ------------------------------------
__global__ void reduce_kernel(const float* __restrict__ part,
                              float* __restrict__ out)
{
    int i = blockIdx.x * blockDim.x + threadIdx.x;
    if (i < NTOK * NDBL) {
        int row = i / NDBL, col = i - row * NDBL;
        float s = 0.f;
#pragma unroll
        for (int z = 0; z < NSPLIT; ++z)
            s += part[(size_t)z * NTOK * NPAD + (size_t)row * NPAD + col];
        out[i] = s;
    }
}

// ---------------- causal depthwise conv -> bf16 split ------------------------
__global__ __launch_bounds__(256)
void dwconv_kernel(const float* __restrict__ xz,
                   const float* __restrict__ dw,
                   __nv_bfloat16* __restrict__ oh,
                   __nv_bfloat16* __restrict__ ol)
{
    int i = blockIdx.x * blockDim.x + threadIdx.x;   // float4 index
    int c = (i & (DI / 4 - 1)) << 2;
    int t = i >> 9;                                   // DI/4 = 512
    int l = t & (LSEQ - 1);
    float4 acc = make_float4(0.f, 0.f, 0.f, 0.f);
#pragma unroll
    for (int j = 0; j < 4; ++j) {
        int lj = l - 3 + j;
        if (lj >= 0) {
            float4 xv = *(const float4*)&xz[(size_t)(t - 3 + j) * 2 * DI + c];
            float4 wv = *(const float4*)&dw[(size_t)j * DI + c];
            acc.x += xv.x * wv.x; acc.y += xv.y * wv.y;
            acc.z += xv.z * wv.z; acc.w += xv.w * wv.w;
        }
    }
    float vs[4] = {acc.x, acc.y, acc.z, acc.w};
    size_t o = (size_t)t * DI + c;
#pragma unroll
    for (int j = 0; j < 4; ++j) {
        __nv_bfloat16 hh = __float2bfloat16(vs[j]);
        oh[o + j] = hh;
        ol[o + j] = __float2bfloat16(vs[j] - __bfloat162float(hh));
    }
}

// ---------------- selective scan (fused epilogue -> bf16 split y) ------------
__global__ __launch_bounds__(256)
void scan_kernel(const float* __restrict__ delta,
                 const float* __restrict__ xc,
                 const float* __restrict__ xz,
                 const float* __restrict__ xdbl,
                 const float* __restrict__ A_log,
                 const float* __restrict__ Dv,
                 __nv_bfloat16* __restrict__ yh,
                 __nv_bfloat16* __restrict__ yl)
{
    __shared__ float sd[2][32][32];
    __shared__ float sx[2][32][32];
    __shared__ float sz[2][32][32];
    __shared__ float sbc[2][32][16];
    __shared__ float sy[32][32];

    const int tid = threadIdx.x;
    const int n   = tid & 7;
    const int cl  = tid >> 3;
    const int c0  = blockIdx.x * 32;
    const int tb  = blockIdx.y * LSEQ;
    const int c   = c0 + cl;

    const float a2 = -expf(A_log[c * DST + n]) * 1.44269504f;
    const float Dc = Dv[c];
    float h = 0.f;

    const int row = tid >> 3;
    const int seg = tid & 7;

    {
        int t = tb + row;
        cp16(&sd[0][row][seg * 4], delta + (size_t)t * DI + c0 + seg * 4);
        cp16(&sx[0][row][seg * 4], xc    + (size_t)t * DI + c0 + seg * 4);
        cp16(&sz[0][row][seg * 4], xz    + (size_t)t * 2 * DI + DI + c0 + seg * 4);
        if (seg < 4)
            cp16(&sbc[0][row][seg * 4], xdbl + (size_t)t * NDBL + DTR + seg * 4);
        asm volatile("cp.async.commit_group;");
    }

    int buf = 0;
    for (int ch = 0; ch < LSEQ / 32; ++ch) {
        if (ch < LSEQ / 32 - 1) {
            int t = tb + (ch + 1) * 32 + row;
            int nb = buf ^ 1;
            cp16(&sd[nb][row][seg * 4], delta + (size_t)t * DI + c0 + seg * 4);
            cp16(&sx[nb][row][seg * 4], xc    + (size_t)t * DI + c0 + seg * 4);
            cp16(&sz[nb][row][seg * 4], xz    + (size_t)t * 2 * DI + DI + c0 + seg * 4);
            if (seg < 4)
                cp16(&sbc[nb][row][seg * 4], xdbl + (size_t)t * NDBL + DTR + seg * 4);
            asm volatile("cp.async.commit_group;");
            asm volatile("cp.async.wait_group 1;");
        } else {
            asm volatile("cp.async.wait_group 0;");
        }
        __syncthreads();

#pragma unroll
        for (int tt = 0; tt < 32; ++tt) {
            float dlt = sd[buf][tt][cl];
            float xcv = sx[buf][tt][cl];
            float dA  = exp2f(dlt * a2);
            float dBu = dlt * sbc[buf][tt][n] * xcv;
            h = fmaf(dA, h, dBu);
            float p = sbc[buf][tt][8 + n] * h;
            p += __shfl_xor_sync(0xffffffffu, p, 1);
            p += __shfl_xor_sync(0xffffffffu, p, 2);
            p += __shfl_xor_sync(0xffffffffu, p, 4);
            if (n == 0) {
                float yv = p + xcv * Dc;
                float zv = sz[buf][tt][cl];
                sy[tt][cl] = yv * (zv / (1.f + expf(-zv)));
            }
        }
        __syncthreads();

#pragma unroll
        for (int r = 0; r < 4; ++r) {
            int e  = r * 256 + tid;
            int tt = e >> 5, col = e & 31;
            float v = sy[tt][col];
            __nv_bfloat16 hh = __float2bfloat16(v);
            size_t o = (size_t)(tb + ch * 32 + tt) * DI + c0 + col;
            yh[o] = hh;
            yl[o] = __float2bfloat16(v - __bfloat162float(hh));
        }
        buf ^= 1;
    }
}

// ---------------------------------------------------------------------------
extern "C" void kernel_launch(void* const* d_in, const int* in_sizes, int n_in,
                              void* d_out, int out_size)
{
    const float* x     = (const float*)d_in[0];
    const float* W_in  = (const float*)d_in[1];
    const float* dw    = (const float*)d_in[2];
    const float* pw    = (const float*)d_in[3];
    const float* cb    = (const float*)d_in[4];
    const float* W_x   = (const float*)d_in[5];
    const float* W_dt  = (const float*)d_in[6];
    const float* b_dt  = (const float*)d_in[7];
    const float* A_log = (const float*)d_in[8];
    const float* Dv    = (const float*)d_in[9];
    const float* W_out = (const float*)d_in[10];
    float* out = (float*)d_out;

    // Resolve scratch addresses on EVERY call (capture-identical behavior).
    float *p_xz, *p_xc, *p_xdbl, *p_wxpad, *p_part, *p_delta;
    __nv_bfloat16 *p_xh, *p_xl, *p_winh, *p_winl, *p_xcph, *p_xcpl;
    __nv_bfloat16 *p_pwh, *p_pwl, *p_yh, *p_yl, *p_woh, *p_wol;
    cudaGetSymbolAddress((void**)&p_xz,    g_xz);
    cudaGetSymbolAddress((void**)&p_xc,    g_xc);
    cudaGetSymbolAddress((void**)&p_xdbl,  g_xdbl);
    cudaGetSymbolAddress((void**)&p_wxpad, g_wxpad);
    cudaGetSymbolAddress((void**)&p_part,  g_part);
    cudaGetSymbolAddress((void**)&p_delta, g_delta);
    cudaGetSymbolAddress((void**)&p_xh,    g_xh);
    cudaGetSymbolAddress((void**)&p_xl,    g_xl);
    cudaGetSymbolAddress((void**)&p_winh,  g_winT_h);
    cudaGetSymbolAddress((void**)&p_winl,  g_winT_l);
    cudaGetSymbolAddress((void**)&p_xcph,  g_xcp_h);
    cudaGetSymbolAddress((void**)&p_xcpl,  g_xcp_l);
    cudaGetSymbolAddress((void**)&p_pwh,   g_pwT_h);
    cudaGetSymbolAddress((void**)&p_pwl,   g_pwT_l);
    cudaGetSymbolAddress((void**)&p_yh,    g_yh);
    cudaGetSymbolAddress((void**)&p_yl,    g_yl);
    cudaGetSymbolAddress((void**)&p_woh,   g_woutT_h);
    cudaGetSymbolAddress((void**)&p_wol,   g_woutT_l);

    // allow 80KB dynamic smem for the merged-phase HMMA kernel
    cudaFuncSetAttribute(hmma_kernel,
                         cudaFuncAttributeMaxDynamicSharedMemorySize, HSMB);

    // weight preprocessing
    tsplit_kernel<<<dim3(2 * DI / 32, DM / 32), 256>>>(W_in, DM, 2 * DI, p_winh, p_winl);
    tsplit_kernel<<<dim3(DI / 32, DI / 32), 256>>>(pw, DI, DI, p_pwh, p_pwl);
    tsplit_kernel<<<dim3(DM / 32, DI / 32), 256>>>(W_out, DI, DM, p_woh, p_wol);
    split_kernel<<<(NTOK * DM / 4 + 255) / 256, 256>>>(x, p_xh, p_xl, NTOK * DM);
    padwx_kernel<<<(DI * NPAD + 255) / 256, 256>>>(W_x, p_wxpad);

    // 1) xz = x @ W_in    (HMMA bf16-split, merged phases)
    hmma_kernel<<<dim3(2 * DI / HTN, NTOK / HTM), 256, HSMB>>>(
        p_xh, p_xl, p_winh, p_winl, p_xz, 2 * DI, NTOK, 2 * DI, DM, nullptr, 0);

    // 2) depthwise causal conv (emits bf16 split directly)
    dwconv_kernel<<<(NTOK * DI / 4) / 256, 256>>>(p_xz, dw, p_xcph, p_xcpl);

    // 3) xc = silu(conv @ pw + cb)   (HMMA bf16-split)
    hmma_kernel<<<dim3(DI / HTN, NTOK / HTM), 256, HSMB>>>(
        p_xcph, p_xcpl, p_pwh, p_pwl, p_xc, DI, NTOK, DI, DI, cb, 1);

    // 4) xdbl = xc @ W_x_pad (fp32 split-K, deterministic)
    sgemm_kernel<<<dim3(1, NTOK / BM, NSPLIT), 256>>>(
        p_xc, DI, p_wxpad, NPAD, p_part, NPAD, (long long)NTOK * NPAD,
        NTOK, NPAD, DI, DI / NSPLIT, nullptr, 0);
    reduce_kernel<<<(NTOK * NDBL + 255) / 256, 256>>>(p_part, p_xdbl);

    // 5) delta = softplus(xdbl[:, :64] @ W_dt + b_dt)  (fp32)
    sgemm_kernel<<<dim3(DI / BN, NTOK / BM), 256>>>(
        p_xdbl, NDBL, W_dt, DI, p_delta, DI, 0, NTOK, DI, DTR, DTR, b_dt, 2);

    // 6) selective scan fused with gating (emits bf16 split y)
    scan_kernel<<<dim3(DI / 32, 2), 256>>>(
        p_delta, p_xc, p_xz, p_xdbl, A_log, Dv, p_yh, p_yl);

    // 7) out = y @ W_out   (HMMA bf16-split)
    hmma_kernel<<<dim3(DM / HTN, NTOK / HTM), 256, HSMB>>>(
        p_yh, p_yl, p_woh, p_wol, out, DM, NTOK, DM, DI, nullptr, 0);
}

// round 17
// speedup vs baseline: 2.2313x; 1.0271x over previous
#include <cuda_runtime.h>
#include <cuda_bf16.h>
#include <math.h>
#include <stdint.h>

// ---------------------------------------------------------------------------
// MambaLayer: B=2, L=2048, D_MODEL=1024, D_INNER=2048, D_STATE=8, D_CONV=4,
// DT_RANK=64.  NTOK = B*L = 4096.
//
// GEMMs 1,3,5,7 on tensor cores via mma.sync (HMMA base ISA) with bf16-split
// fp32 emulation: A=Ah+Al, B=Bh+Bl -> D = AhBh + AhBl + AlBh (fp32 reg acc).
// Merged-phase mainloop: 4 tiles staged once per K-block, 3 products issued.
// GEMM4 stays on the fp32 FFMA2 split-K path.
// ---------------------------------------------------------------------------

#define NTOK   4096
#define DI     2048
#define DM     1024
#define NDBL   80       // DT_RANK + 2*D_STATE
#define NPAD   128      // padded N for GEMM4
#define DTR    64
#define DST    8
#define NSPLIT 8
#define LSEQ   2048

// ---------------- scratch (device globals: no runtime allocs) --------------
__device__ float g_xz   [(size_t)NTOK * 2 * DI];
__device__ float g_xc   [(size_t)NTOK * DI];
__device__ float g_xdbl [(size_t)NTOK * NDBL];
__device__ float g_wxpad[(size_t)DI * NPAD];
__device__ float g_part [(size_t)NSPLIT * NTOK * NPAD];
__device__ float g_delta[(size_t)NTOK * DI];

// bf16 split buffers
__device__ __nv_bfloat16 g_xh    [(size_t)NTOK * DM];
__device__ __nv_bfloat16 g_xl    [(size_t)NTOK * DM];
__device__ __nv_bfloat16 g_winT_h[(size_t)(2 * DI) * DM];   // [N=4096, K=1024]
__device__ __nv_bfloat16 g_winT_l[(size_t)(2 * DI) * DM];
__device__ __nv_bfloat16 g_xcp_h [(size_t)NTOK * DI];
__device__ __nv_bfloat16 g_xcp_l [(size_t)NTOK * DI];
__device__ __nv_bfloat16 g_pwT_h [(size_t)DI * DI];         // [N=2048, K=2048]
__device__ __nv_bfloat16 g_pwT_l [(size_t)DI * DI];
__device__ __nv_bfloat16 g_yh    [(size_t)NTOK * DI];
__device__ __nv_bfloat16 g_yl    [(size_t)NTOK * DI];
__device__ __nv_bfloat16 g_woutT_h[(size_t)DM * DI];        // [N=1024, K=2048]
__device__ __nv_bfloat16 g_woutT_l[(size_t)DM * DI];
__device__ __nv_bfloat16 g_xdh   [(size_t)NTOK * DTR];      // xdbl[:, :64] split
__device__ __nv_bfloat16 g_xdl   [(size_t)NTOK * DTR];
__device__ __nv_bfloat16 g_wdtT_h[(size_t)DI * DTR];        // [N=2048, K=64]
__device__ __nv_bfloat16 g_wdtT_l[(size_t)DI * DTR];

// ---------------- small helpers --------------------------------------------
__device__ __forceinline__ unsigned long long pack2(float lo, float hi) {
    unsigned long long r;
    asm("mov.b64 %0, {%1, %2};" : "=l"(r) : "f"(lo), "f"(hi));
    return r;
}
__device__ __forceinline__ void unpack2(unsigned long long v, float &lo, float &hi) {
    asm("mov.b64 {%0, %1}, %2;" : "=f"(lo), "=f"(hi) : "l"(v));
}
__device__ __forceinline__ void ffma2(unsigned long long &d,
                                      unsigned long long a,
                                      unsigned long long b) {
    asm("fma.rn.f32x2 %0, %1, %2, %0;" : "+l"(d) : "l"(a), "l"(b));
}
__device__ __forceinline__ void cp16(void* s, const void* g) {
    unsigned saddr = (unsigned)__cvta_generic_to_shared(s);
    asm volatile("cp.async.ca.shared.global [%0], [%1], 16;" :: "r"(saddr), "l"(g));
}
__device__ __forceinline__ float apply_epi(float x, int epi) {
    if (epi == 1) return x / (1.f + expf(-x));                  // silu
    if (epi == 2) return (x > 20.f) ? x : log1pf(expf(x));      // softplus
    return x;
}

// ---------------- HMMA (mma.sync) bf16-split GEMM, merged phases ------------
// C[M,N] = A[M,K] @ B^T with BT given as [N,K] (k-major both sides).
// Tile 128x128x32, 256 thr = 8 warps (4 m x 2 n), warp tile 32x64.
#define HTM 128
#define HTN 128
#define HTK 32
#define ASTR 40            // bf16 per smem row (32 data + 8 pad = 80 B)
#define TILEE (HTM * ASTR) // 5120 bf16 = 10240 B per tile
#define HSME  (2 * 4 * TILEE)            // elements: 2 stages x 4 tiles
#define HSMB  (HSME * 2)                 // 81920 bytes dynamic smem

#define LDSM4(r0, r1, r2, r3, addr) \
    asm volatile("ldmatrix.sync.aligned.m8n8.x4.shared.b16 {%0,%1,%2,%3}, [%4];" \
        : "=r"(r0), "=r"(r1), "=r"(r2), "=r"(r3) : "r"(addr))

#define MMA16816(c, a, b) \
    asm volatile("mma.sync.aligned.m16n8k16.row.col.f32.bf16.bf16.f32 " \
        "{%0,%1,%2,%3}, {%4,%5,%6,%7}, {%8,%9}, {%0,%1,%2,%3};" \
        : "+f"((c)[0]), "+f"((c)[1]), "+f"((c)[2]), "+f"((c)[3]) \
        : "r"((a)[0]), "r"((a)[1]), "r"((a)[2]), "r"((a)[3]), \
          "r"((b)[0]), "r"((b)[1]))

__global__ __launch_bounds__(256, 2)
void hmma_kernel(const __nv_bfloat16* __restrict__ Ah,
                 const __nv_bfloat16* __restrict__ Al,
                 const __nv_bfloat16* __restrict__ BhT,
                 const __nv_bfloat16* __restrict__ BlT,
                 float* __restrict__ C, int ldc,
                 int M, int N, int K,
                 const float* __restrict__ bias, int epi)
{
    extern __shared__ __nv_bfloat16 sm[];

    const int tid  = threadIdx.x;
    const int wid  = tid >> 5, lane = tid & 31;
    const int wm   = wid & 3, wn = wid >> 2;
    const int m0   = blockIdx.y * HTM;
    const int n0   = blockIdx.x * HTN;

    const int kiters = K / HTK;

    float acc[2][8][4];
#pragma unroll
    for (int i = 0; i < 2; ++i)
#pragma unroll
        for (int j = 0; j < 8; ++j)
#pragma unroll
            for (int t = 0; t < 4; ++t) acc[i][j][t] = 0.f;

    auto issue = [&](int it) {
        const int kb = it * HTK;
        __nv_bfloat16* st = sm + (it & 1) * 4 * TILEE;
#pragma unroll
        for (int q = tid; q < 512; q += 256) {
            const int row = q >> 2, cc = (q & 3) << 3;   // 8 bf16 = 16B chunk
            const size_t ga = (size_t)(m0 + row) * K + kb + cc;
            const size_t gb = (size_t)(n0 + row) * K + kb + cc;
            const int so = row * ASTR + cc;
            cp16(st + so,             Ah  + ga);
            cp16(st + TILEE + so,     Al  + ga);
            cp16(st + 2 * TILEE + so, BhT + gb);
            cp16(st + 3 * TILEE + so, BlT + gb);
        }
        asm volatile("cp.async.commit_group;");
    };

    issue(0);
    for (int it = 0; it < kiters; ++it) {
        asm volatile("cp.async.wait_group 0;");
        __syncthreads();
        if (it + 1 < kiters) issue(it + 1);   // overlaps with compute below

        __nv_bfloat16* st = sm + (it & 1) * 4 * TILEE;
        const uint32_t ah_b = (uint32_t)__cvta_generic_to_shared(st);
        const uint32_t al_b = ah_b + TILEE * 2u;
        const uint32_t bh_b = ah_b + 2u * TILEE * 2u;
        const uint32_t bl_b = ah_b + 3u * TILEE * 2u;

#pragma unroll
        for (int k16 = 0; k16 < 2; ++k16) {
            const uint32_t aoff =
                (((uint32_t)(wm * 32 + (lane & 15))) * ASTR +
                 ((lane >> 4) << 3) + k16 * 16) * 2u;
            const uint32_t boff0 =
                (((uint32_t)(wn * 64 + ((lane >> 4) << 3) + (lane & 7))) * ASTR +
                 (((lane >> 3) & 1) << 3) + k16 * 16) * 2u;

            uint32_t a1[2][4], a2[2][4], bb[8][2];
            // --- ah, bh ---
#pragma unroll
            for (int mi = 0; mi < 2; ++mi)
                LDSM4(a1[mi][0], a1[mi][1], a1[mi][2], a1[mi][3],
                      ah_b + aoff + (uint32_t)(mi * 16 * ASTR) * 2u);
#pragma unroll
            for (int nb = 0; nb < 4; ++nb) {
                uint32_t r0, r1, r2, r3;
                LDSM4(r0, r1, r2, r3,
                      bh_b + boff0 + (uint32_t)(nb * 16 * ASTR) * 2u);
                bb[nb * 2][0] = r0;     bb[nb * 2][1] = r1;
                bb[nb * 2 + 1][0] = r2; bb[nb * 2 + 1][1] = r3;
            }
#pragma unroll
            for (int mi = 0; mi < 2; ++mi)
#pragma unroll
                for (int nj = 0; nj < 8; ++nj)
                    MMA16816(acc[mi][nj], a1[mi], bb[nj]);
            // --- al x bh ---
#pragma unroll
            for (int mi = 0; mi < 2; ++mi)
                LDSM4(a2[mi][0], a2[mi][1], a2[mi][2], a2[mi][3],
                      al_b + aoff + (uint32_t)(mi * 16 * ASTR) * 2u);
#pragma unroll
            for (int mi = 0; mi < 2; ++mi)
#pragma unroll
                for (int nj = 0; nj < 8; ++nj)
                    MMA16816(acc[mi][nj], a2[mi], bb[nj]);
            // --- ah x bl (bl overwrites bh frags) ---
#pragma unroll
            for (int nb = 0; nb < 4; ++nb) {
                uint32_t r0, r1, r2, r3;
                LDSM4(r0, r1, r2, r3,
                      bl_b + boff0 + (uint32_t)(nb * 16 * ASTR) * 2u);
                bb[nb * 2][0] = r0;     bb[nb * 2][1] = r1;
                bb[nb * 2 + 1][0] = r2; bb[nb * 2 + 1][1] = r3;
            }
#pragma unroll
            for (int mi = 0; mi < 2; ++mi)
#pragma unroll
                for (int nj = 0; nj < 8; ++nj)
                    MMA16816(acc[mi][nj], a1[mi], bb[nj]);
        }
        // NOTE: no bottom __syncthreads needed — the top barrier of the next
        // iteration orders each thread's compute (program order) against any
        // later overwrite of this slot (issue(it+2) follows that barrier).
    }

    // epilogue: c frag (m16n8): c0,c1 at (row=lane/4, col=2*(lane%4)+{0,1}),
    //           c2,c3 at row+8.
    const int rbase = m0 + wm * 32;
    const int cb0   = n0 + wn * 64 + ((lane & 3) << 1);
#pragma unroll
    for (int mi = 0; mi < 2; ++mi) {
        const int r0 = rbase + mi * 16 + (lane >> 2);
#pragma unroll
        for (int nj = 0; nj < 8; ++nj) {
            const int col = cb0 + nj * 8;
            float b0 = 0.f, b1 = 0.f;
            if (bias) { b0 = bias[col]; b1 = bias[col + 1]; }
            float2 v0, v1;
            v0.x = apply_epi(acc[mi][nj][0] + b0, epi);
            v0.y = apply_epi(acc[mi][nj][1] + b1, epi);
            v1.x = apply_epi(acc[mi][nj][2] + b0, epi);
            v1.y = apply_epi(acc[mi][nj][3] + b1, epi);
            *(float2*)&C[(size_t)r0 * ldc + col]       = v0;
            *(float2*)&C[(size_t)(r0 + 8) * ldc + col] = v1;
        }
    }
}

// ---------------- fp32 tiled SGEMM (GEMM4) ----------------------------------
#define BM 128
#define BN 128
#define BK 16

__global__ __launch_bounds__(256, 2)
void sgemm_kernel(const float* __restrict__ A, int lda,
                  const float* __restrict__ B, int ldb,
                  float* __restrict__ C, int ldc, long long zstride,
                  int M, int N, int K, int kChunk,
                  const float* __restrict__ bias, int epi)
{
    __shared__ float As[BK][BM + 4];
    __shared__ float Bs[BK][BN];

    const int tid = threadIdx.x;
    const int ty = tid >> 4;
    const int tx = tid & 15;
    const int m0 = blockIdx.y * BM;
    const int n0 = blockIdx.x * BN;
    const int k0 = blockIdx.z * kChunk;
    const int k1 = (k0 + kChunk < K) ? (k0 + kChunk) : K;
    C += (long long)blockIdx.z * zstride;

    const int a_r0 = tid >> 2,          a_c0 = (tid & 3) << 2;
    const int a_r1 = (tid + 256) >> 2,  a_c1 = ((tid + 256) & 3) << 2;
    const int b_r0 = tid >> 5,          b_c0 = (tid & 31) << 2;
    const int b_r1 = (tid + 256) >> 5,  b_c1 = ((tid + 256) & 31) << 2;

    float4 avA, avB, bvA, bvB;

    unsigned long long acc[8][4];
#pragma unroll
    for (int i = 0; i < 8; ++i)
#pragma unroll
        for (int j = 0; j < 4; ++j) acc[i][j] = 0ull;

#define LOAD_TILE(kb) do {                                                       \
    avA = *(const float4*)&A[(size_t)(m0 + a_r0) * lda + (kb) + a_c0];           \
    avB = *(const float4*)&A[(size_t)(m0 + a_r1) * lda + (kb) + a_c1];           \
    bvA = *(const float4*)&B[(size_t)((kb) + b_r0) * ldb + n0 + b_c0];           \
    bvB = *(const float4*)&B[(size_t)((kb) + b_r1) * ldb + n0 + b_c1];           \
    } while (0)

#define STORE_TILE() do {                                                        \
    As[a_c0 + 0][a_r0] = avA.x; As[a_c0 + 1][a_r0] = avA.y;                      \
    As[a_c0 + 2][a_r0] = avA.z; As[a_c0 + 3][a_r0] = avA.w;                      \
    As[a_c1 + 0][a_r1] = avB.x; As[a_c1 + 1][a_r1] = avB.y;                      \
    As[a_c1 + 2][a_r1] = avB.z; As[a_c1 + 3][a_r1] = avB.w;                      \
    *(float4*)&Bs[b_r0][b_c0] = bvA;                                             \
    *(float4*)&Bs[b_r1][b_c1] = bvB;                                             \
    } while (0)

    LOAD_TILE(k0);
    STORE_TILE();
    __syncthreads();

    for (int kb = k0; kb < k1; kb += BK) {
        const bool more = (kb + BK < k1);
        if (more) LOAD_TILE(kb + BK);

#pragma unroll
        for (int kk = 0; kk < BK; ++kk) {
            float4 a0 = *(const float4*)&As[kk][ty * 8];
            float4 a1 = *(const float4*)&As[kk][ty * 8 + 4];
            const unsigned long long* bp =
                (const unsigned long long*)&Bs[kk][tx * 8];
            unsigned long long b0 = bp[0], b1 = bp[1], b2 = bp[2], b3 = bp[3];
            float ar[8] = {a0.x, a0.y, a0.z, a0.w, a1.x, a1.y, a1.z, a1.w};
#pragma unroll
            for (int i = 0; i < 8; ++i) {
                unsigned long long aa = pack2(ar[i], ar[i]);
                ffma2(acc[i][0], aa, b0);
                ffma2(acc[i][1], aa, b1);
                ffma2(acc[i][2], aa, b2);
                ffma2(acc[i][3], aa, b3);
            }
        }
        __syncthreads();
        if (more) { STORE_TILE(); __syncthreads(); }
    }

    const int cbase = n0 + tx * 8;
#pragma unroll
    for (int i = 0; i < 8; ++i) {
        const int row = m0 + ty * 8 + i;
        float v[8];
#pragma unroll
        for (int j = 0; j < 4; ++j) unpack2(acc[i][j], v[2 * j], v[2 * j + 1]);
#pragma unroll
        for (int t = 0; t < 8; ++t) {
            float xv = v[t];
            if (bias) xv += bias[cbase + t];
            v[t] = apply_epi(xv, epi);
        }
        *(float4*)&C[(size_t)row * ldc + cbase]     = make_float4(v[0], v[1], v[2], v[3]);
        *(float4*)&C[(size_t)row * ldc + cbase + 4] = make_float4(v[4], v[5], v[6], v[7]);
    }
#undef LOAD_TILE
#undef STORE_TILE
}

// ---------------- conversion kernels ----------------------------------------
__global__ void split_kernel(const float* __restrict__ src,
                             __nv_bfloat16* __restrict__ h,
                             __nv_bfloat16* __restrict__ l, int n)
{
    int i = blockIdx.x * blockDim.x + threadIdx.x;      // float4 index
    if (i * 4 < n) {
        float4 v = *(const float4*)&src[i * 4];
        float vs[4] = {v.x, v.y, v.z, v.w};
        __nv_bfloat16 hh[4], ll[4];
#pragma unroll
        for (int j = 0; j < 4; ++j) {
            hh[j] = __float2bfloat16(vs[j]);
            ll[j] = __float2bfloat16(vs[j] - __bfloat162float(hh[j]));
        }
        *(uint2*)&h[i * 4] = *(uint2*)hh;
        *(uint2*)&l[i * 4] = *(uint2*)ll;
    }
}

// transpose + split: src[K,N] fp32 -> hT,lT [N,K] bf16
__global__ __launch_bounds__(256)
void tsplit_kernel(const float* __restrict__ src, int K, int N,
                   __nv_bfloat16* __restrict__ hT,
                   __nv_bfloat16* __restrict__ lT)
{
    __shared__ float t[32][33];
    const int bx = blockIdx.x * 32;   // N
    const int by = blockIdx.y * 32;   // K
    const int tx = threadIdx.x & 31, ty = threadIdx.x >> 5;   // ty 0..7
#pragma unroll
    for (int j = 0; j < 32; j += 8)
        t[ty + j][tx] = src[(size_t)(by + ty + j) * N + bx + tx];
    __syncthreads();
#pragma unroll
    for (int j = 0; j < 32; j += 8) {
        float v = t[tx][ty + j];
        __nv_bfloat16 hh = __float2bfloat16(v);
        size_t o = (size_t)(bx + ty + j) * K + by + tx;
        hT[o] = hh;
        lT[o] = __float2bfloat16(v - __bfloat162float(hh));
    }
}

// ---------------- W_x pad: [2048,80] -> [2048,128] --------------------------
__global__ void padwx_kernel(const float* __restrict__ wx,
                             float* __restrict__ wp)
{
    int i = blockIdx.x * blockDim.x + threadIdx.x;
    if (i < DI * NPAD) {
        int r = i >> 7, c = i & (NPAD - 1);
        wp[i] = (c < NDBL) ? wx[r * NDBL + c] : 0.f;
    }
}

// ---------------- split-K partial reduce (+ bf16 split of delta cols) -------
__global__ void reduce_kernel(const float* __restrict__ part,
                              float* __restrict__ out,
                              __nv_bfloat16* __restrict__ xdh,
                              __nv_bfloat16* __restrict__ xdl)
{
    int i = blockIdx.x * blockDim.x + threadIdx.x;
    if (i < NTOK * NDBL) {
        int row = i / NDBL, col = i - row * NDBL;
        float s = 0.f;
#pragma unroll
        for (int z = 0; z < NSPLIT; ++z)
            s += part[(size_t)z * NTOK * NPAD + (size_t)row * NPAD + col];
        out[i] = s;
        if (col < DTR) {
            __nv_bfloat16 hh = __float2bfloat16(s);
            size_t o = (size_t)row * DTR + col;
            xdh[o] = hh;
            xdl[o] = __float2bfloat16(s - __bfloat162float(hh));
        }
    }
}

// ---------------- causal depthwise conv -> bf16 split ------------------------
__global__ __launch_bounds__(256)
void dwconv_kernel(const float* __restrict__ xz,
                   const float* __restrict__ dw,
                   __nv_bfloat16* __restrict__ oh,
                   __nv_bfloat16* __restrict__ ol)
{
    int i = blockIdx.x * blockDim.x + threadIdx.x;   // float4 index
    int c = (i & (DI / 4 - 1)) << 2;
    int t = i >> 9;                                   // DI/4 = 512
    int l = t & (LSEQ - 1);
    float4 acc = make_float4(0.f, 0.f, 0.f, 0.f);
#pragma unroll
    for (int j = 0; j < 4; ++j) {
        int lj = l - 3 + j;
        if (lj >= 0) {
            float4 xv = *(const float4*)&xz[(size_t)(t - 3 + j) * 2 * DI + c];
            float4 wv = *(const float4*)&dw[(size_t)j * DI + c];
            acc.x += xv.x * wv.x; acc.y += xv.y * wv.y;
            acc.z += xv.z * wv.z; acc.w += xv.w * wv.w;
        }
    }
    float vs[4] = {acc.x, acc.y, acc.z, acc.w};
    size_t o = (size_t)t * DI + c;
#pragma unroll
    for (int j = 0; j < 4; ++j) {
        __nv_bfloat16 hh = __float2bfloat16(vs[j]);
        oh[o + j] = hh;
        ol[o + j] = __float2bfloat16(vs[j] - __bfloat162float(hh));
    }
}

// ---------------- selective scan (fused epilogue -> bf16 split y) ------------
__global__ __launch_bounds__(256)
void scan_kernel(const float* __restrict__ delta,
                 const float* __restrict__ xc,
                 const float* __restrict__ xz,
                 const float* __restrict__ xdbl,
                 const float* __restrict__ A_log,
                 const float* __restrict__ Dv,
                 __nv_bfloat16* __restrict__ yh,
                 __nv_bfloat16* __restrict__ yl)
{
    __shared__ float sd[2][32][32];
    __shared__ float sx[2][32][32];
    __shared__ float sz[2][32][32];
    __shared__ float sbc[2][32][16];
    __shared__ float sy[32][32];

    const int tid = threadIdx.x;
    const int n   = tid & 7;
    const int cl  = tid >> 3;
    const int c0  = blockIdx.x * 32;
    const int tb  = blockIdx.y * LSEQ;
    const int c   = c0 + cl;

    const float a2 = -expf(A_log[c * DST + n]) * 1.44269504f;
    const float Dc = Dv[c];
    float h = 0.f;

    const int row = tid >> 3;
    const int seg = tid & 7;

    {
        int t = tb + row;
        cp16(&sd[0][row][seg * 4], delta + (size_t)t * DI + c0 + seg * 4);
        cp16(&sx[0][row][seg * 4], xc    + (size_t)t * DI + c0 + seg * 4);
        cp16(&sz[0][row][seg * 4], xz    + (size_t)t * 2 * DI + DI + c0 + seg * 4);
        if (seg < 4)
            cp16(&sbc[0][row][seg * 4], xdbl + (size_t)t * NDBL + DTR + seg * 4);
        asm volatile("cp.async.commit_group;");
    }

    int buf = 0;
    for (int ch = 0; ch < LSEQ / 32; ++ch) {
        if (ch < LSEQ / 32 - 1) {
            int t = tb + (ch + 1) * 32 + row;
            int nb = buf ^ 1;
            cp16(&sd[nb][row][seg * 4], delta + (size_t)t * DI + c0 + seg * 4);
            cp16(&sx[nb][row][seg * 4], xc    + (size_t)t * DI + c0 + seg * 4);
            cp16(&sz[nb][row][seg * 4], xz    + (size_t)t * 2 * DI + DI + c0 + seg * 4);
            if (seg < 4)
                cp16(&sbc[nb][row][seg * 4], xdbl + (size_t)t * NDBL + DTR + seg * 4);
            asm volatile("cp.async.commit_group;");
            asm volatile("cp.async.wait_group 1;");
        } else {
            asm volatile("cp.async.wait_group 0;");
        }
        __syncthreads();

#pragma unroll
        for (int tt = 0; tt < 32; ++tt) {
            float dlt = sd[buf][tt][cl];
            float xcv = sx[buf][tt][cl];
            float dA  = exp2f(dlt * a2);
            float dBu = dlt * sbc[buf][tt][n] * xcv;
            h = fmaf(dA, h, dBu);
            float p = sbc[buf][tt][8 + n] * h;
            p += __shfl_xor_sync(0xffffffffu, p, 1);
            p += __shfl_xor_sync(0xffffffffu, p, 2);
            p += __shfl_xor_sync(0xffffffffu, p, 4);
            if (n == 0) {
                float yv = p + xcv * Dc;
                float zv = sz[buf][tt][cl];
                sy[tt][cl] = yv * (zv / (1.f + expf(-zv)));
            }
        }
        __syncthreads();

#pragma unroll
        for (int r = 0; r < 4; ++r) {
            int e  = r * 256 + tid;
            int tt = e >> 5, col = e & 31;
            float v = sy[tt][col];
            __nv_bfloat16 hh = __float2bfloat16(v);
            size_t o = (size_t)(tb + ch * 32 + tt) * DI + c0 + col;
            yh[o] = hh;
            yl[o] = __float2bfloat16(v - __bfloat162float(hh));
        }
        buf ^= 1;
    }
}

// ---------------------------------------------------------------------------
extern "C" void kernel_launch(void* const* d_in, const int* in_sizes, int n_in,
                              void* d_out, int out_size)
{
    const float* x     = (const float*)d_in[0];
    const float* W_in  = (const float*)d_in[1];
    const float* dw    = (const float*)d_in[2];
    const float* pw    = (const float*)d_in[3];
    const float* cb    = (const float*)d_in[4];
    const float* W_x   = (const float*)d_in[5];
    const float* W_dt  = (const float*)d_in[6];
    const float* b_dt  = (const float*)d_in[7];
    const float* A_log = (const float*)d_in[8];
    const float* Dv    = (const float*)d_in[9];
    const float* W_out = (const float*)d_in[10];
    float* out = (float*)d_out;

    // Resolve scratch addresses on EVERY call (capture-identical behavior).
    float *p_xz, *p_xc, *p_xdbl, *p_wxpad, *p_part, *p_delta;
    __nv_bfloat16 *p_xh, *p_xl, *p_winh, *p_winl, *p_xcph, *p_xcpl;
    __nv_bfloat16 *p_pwh, *p_pwl, *p_yh, *p_yl, *p_woh, *p_wol;
    __nv_bfloat16 *p_xdh, *p_xdl, *p_wdth, *p_wdtl;
    cudaGetSymbolAddress((void**)&p_xz,    g_xz);
    cudaGetSymbolAddress((void**)&p_xc,    g_xc);
    cudaGetSymbolAddress((void**)&p_xdbl,  g_xdbl);
    cudaGetSymbolAddress((void**)&p_wxpad, g_wxpad);
    cudaGetSymbolAddress((void**)&p_part,  g_part);
    cudaGetSymbolAddress((void**)&p_delta, g_delta);
    cudaGetSymbolAddress((void**)&p_xh,    g_xh);
    cudaGetSymbolAddress((void**)&p_xl,    g_xl);
    cudaGetSymbolAddress((void**)&p_winh,  g_winT_h);
    cudaGetSymbolAddress((void**)&p_winl,  g_winT_l);
    cudaGetSymbolAddress((void**)&p_xcph,  g_xcp_h);
    cudaGetSymbolAddress((void**)&p_xcpl,  g_xcp_l);
    cudaGetSymbolAddress((void**)&p_pwh,   g_pwT_h);
    cudaGetSymbolAddress((void**)&p_pwl,   g_pwT_l);
    cudaGetSymbolAddress((void**)&p_yh,    g_yh);
    cudaGetSymbolAddress((void**)&p_yl,    g_yl);
    cudaGetSymbolAddress((void**)&p_woh,   g_woutT_h);
    cudaGetSymbolAddress((void**)&p_wol,   g_woutT_l);
    cudaGetSymbolAddress((void**)&p_xdh,   g_xdh);
    cudaGetSymbolAddress((void**)&p_xdl,   g_xdl);
    cudaGetSymbolAddress((void**)&p_wdth,  g_wdtT_h);
    cudaGetSymbolAddress((void**)&p_wdtl,  g_wdtT_l);

    // allow 80KB dynamic smem for the merged-phase HMMA kernel
    cudaFuncSetAttribute(hmma_kernel,
                         cudaFuncAttributeMaxDynamicSharedMemorySize, HSMB);

    // --- preprocessing needed by GEMM1 only (keeps hmma1 in the profiled slot)
    tsplit_kernel<<<dim3(2 * DI / 32, DM / 32), 256>>>(W_in, DM, 2 * DI, p_winh, p_winl);
    split_kernel<<<(NTOK * DM / 4 + 255) / 256, 256>>>(x, p_xh, p_xl, NTOK * DM);
    padwx_kernel<<<(DI * NPAD + 255) / 256, 256>>>(W_x, p_wxpad);

    // 1) xz = x @ W_in    (HMMA bf16-split, merged phases)  [profiled launch]
    hmma_kernel<<<dim3(2 * DI / HTN, NTOK / HTM), 256, HSMB>>>(
        p_xh, p_xl, p_winh, p_winl, p_xz, 2 * DI, NTOK, 2 * DI, DM, nullptr, 0);

    // --- remaining weight preprocessing (overlaps nothing; cheap)
    tsplit_kernel<<<dim3(DI / 32, DI / 32), 256>>>(pw, DI, DI, p_pwh, p_pwl);
    tsplit_kernel<<<dim3(DM / 32, DI / 32), 256>>>(W_out, DI, DM, p_woh, p_wol);
    tsplit_kernel<<<dim3(DI / 32, DTR / 32), 256>>>(W_dt, DTR, DI, p_wdth, p_wdtl);

    // 2) depthwise causal conv (emits bf16 split directly)
    dwconv_kernel<<<(NTOK * DI / 4) / 256, 256>>>(p_xz, dw, p_xcph, p_xcpl);

    // 3) xc = silu(conv @ pw + cb)   (HMMA bf16-split)
    hmma_kernel<<<dim3(DI / HTN, NTOK / HTM), 256, HSMB>>>(
        p_xcph, p_xcpl, p_pwh, p_pwl, p_xc, DI, NTOK, DI, DI, cb, 1);

    // 4) xdbl = xc @ W_x_pad (fp32 split-K, deterministic; reduce also emits
    //    bf16 split of the delta columns for GEMM5)
    sgemm_kernel<<<dim3(1, NTOK / BM, NSPLIT), 256>>>(
        p_xc, DI, p_wxpad, NPAD, p_part, NPAD, (long long)NTOK * NPAD,
        NTOK, NPAD, DI, DI / NSPLIT, nullptr, 0);
    reduce_kernel<<<(NTOK * NDBL + 255) / 256, 256>>>(p_part, p_xdbl, p_xdh, p_xdl);

    // 5) delta = softplus(xdbl[:, :64] @ W_dt + b_dt)  (HMMA, K=64)
    hmma_kernel<<<dim3(DI / HTN, NTOK / HTM), 256, HSMB>>>(
        p_xdh, p_xdl, p_wdth, p_wdtl, p_delta, DI, NTOK, DI, DTR, b_dt, 2);

    // 6) selective scan fused with gating (emits bf16 split y)
    scan_kernel<<<dim3(DI / 32, 2), 256>>>(
        p_delta, p_xc, p_xz, p_xdbl, A_log, Dv, p_yh, p_yl);

    // 7) out = y @ W_out   (HMMA bf16-split)
    hmma_kernel<<<dim3(DM / HTN, NTOK / HTM), 256, HSMB>>>(
        p_yh, p_yl, p_woh, p_wol, out, DM, NTOK, DM, DI, nullptr, 0);
}